// round 3
// baseline (speedup 1.0000x reference)
#include <cuda_runtime.h>

// Problem constants
#define BB   4
#define CC   512
#define NN   4096
#define MIDD 64
#define QKV  640   // 64 (q) + 64 (k) + 512 (v)

// Scratch (allocation-free rule: __device__ globals)
// g_qkv[b][n][0:64]   = q[b,n,m]
// g_qkv[b][n][64:128] = k[b,m,n]  (i.e. K^T row n)
// g_qkv[b][n][128:640]= v[b,d,n]  (i.e. V^T row n)
__device__ float g_qkv[(size_t)BB * NN * QKV];          // 40 MB
__device__ float g_p[(size_t)BB * NN * NN];             // 256 MB (logits -> probs)

// ---------------------------------------------------------------------------
// Kernel 1: fused QKV projection.  out[b][n][m] = sum_c W(m,c) * x[b][c][n] + bias(m)
// Tile: 64 (n, ty side) x 64 (m, tx side), K-tile 16. 256 threads, 4x4 micro-tile.
// ---------------------------------------------------------------------------
__global__ __launch_bounds__(256, 4)
void proj_kernel(const float* __restrict__ x,
                 const float* __restrict__ wq, const float* __restrict__ bq,
                 const float* __restrict__ wk, const float* __restrict__ bk,
                 const float* __restrict__ wv, const float* __restrict__ bv) {
    const int n0 = blockIdx.x * 64;
    const int m0 = blockIdx.y * 64;
    const int b  = blockIdx.z;

    const float* W;  const float* bias;  int wr0;
    if (m0 < 64)        { W = wq; bias = bq; wr0 = m0; }
    else if (m0 < 128)  { W = wk; bias = bk; wr0 = m0 - 64; }
    else                { W = wv; bias = bv; wr0 = m0 - 128; }

    __shared__ float xs[16][68];   // [kk][nn]  (broadcast side)
    __shared__ float ws[16][68];   // [kk][mm]  (float4 side)

    const int tid = threadIdx.x;
    const int tx = tid & 15, ty = tid >> 4;

    float acc[4][4] = {};
    const float* xb = x + (size_t)b * CC * NN;

    for (int c0 = 0; c0 < CC; c0 += 16) {
        #pragma unroll
        for (int i = tid; i < 1024; i += 256) {
            int kk = i >> 6, nn = i & 63;
            xs[kk][nn] = xb[(size_t)(c0 + kk) * NN + n0 + nn];
        }
        #pragma unroll
        for (int i = tid; i < 1024; i += 256) {
            int kk = i & 15, mm = i >> 4;
            ws[kk][mm] = W[(wr0 + mm) * CC + c0 + kk];
        }
        __syncthreads();
        #pragma unroll
        for (int kk = 0; kk < 16; kk++) {
            float4 a4 = *(const float4*)&xs[kk][ty * 4];
            float4 b4 = *(const float4*)&ws[kk][tx * 4];
            float a[4] = {a4.x, a4.y, a4.z, a4.w};
            float bv4[4] = {b4.x, b4.y, b4.z, b4.w};
            #pragma unroll
            for (int i = 0; i < 4; i++)
                #pragma unroll
                for (int j = 0; j < 4; j++)
                    acc[i][j] += a[i] * bv4[j];
        }
        __syncthreads();
    }

    float bs[4];
    #pragma unroll
    for (int j = 0; j < 4; j++) bs[j] = bias[wr0 + tx * 4 + j];

    float* ob = g_qkv + ((size_t)b * NN + n0) * QKV + m0;
    #pragma unroll
    for (int i = 0; i < 4; i++) {
        float4 o;
        o.x = acc[i][0] + bs[0];
        o.y = acc[i][1] + bs[1];
        o.z = acc[i][2] + bs[2];
        o.w = acc[i][3] + bs[3];
        *(float4*)&ob[(size_t)(ty * 4 + i) * QKV + tx * 4] = o;
    }
}

// ---------------------------------------------------------------------------
// Kernel 2: logits S[b][i][j] = sum_m q[b,i,m] * k[b,m,j]   (K = 64, one pass)
// Tile 64(i, ty) x 64(j, tx). 256 threads, 4x4 micro-tile.
// ---------------------------------------------------------------------------
__global__ __launch_bounds__(256, 4)
void logits_kernel() {
    const int j0 = blockIdx.x * 64;
    const int i0 = blockIdx.y * 64;
    const int b  = blockIdx.z;

    __shared__ float qs[64][65];   // [m][i]  (broadcast side, scalar reads)
    __shared__ float ks[64][68];   // [m][j]  (float4 side)

    const int tid = threadIdx.x;
    const int tx = tid & 15, ty = tid >> 4;

    const float* base = g_qkv + (size_t)b * NN * QKV;
    #pragma unroll
    for (int idx = tid; idx < 4096; idx += 256) {
        int r = idx >> 6, mm = idx & 63;   // r = local row, mm = contiguous dim
        qs[mm][r] = base[(size_t)(i0 + r) * QKV + mm];
        ks[mm][r] = base[(size_t)(j0 + r) * QKV + 64 + mm];
    }
    __syncthreads();

    float acc[4][4] = {};
    #pragma unroll
    for (int mm = 0; mm < 64; mm++) {
        float a[4];
        #pragma unroll
        for (int i = 0; i < 4; i++) a[i] = qs[mm][ty * 4 + i];
        float4 b4 = *(const float4*)&ks[mm][tx * 4];
        float bv4[4] = {b4.x, b4.y, b4.z, b4.w};
        #pragma unroll
        for (int i = 0; i < 4; i++)
            #pragma unroll
            for (int j = 0; j < 4; j++)
                acc[i][j] += a[i] * bv4[j];
    }

    float* pb = g_p + ((size_t)b * NN + i0) * NN + j0;
    #pragma unroll
    for (int i = 0; i < 4; i++) {
        float4 o = {acc[i][0], acc[i][1], acc[i][2], acc[i][3]};
        *(float4*)&pb[(size_t)(ty * 4 + i) * NN + tx * 4] = o;
    }
}

// ---------------------------------------------------------------------------
// Kernel 3: row softmax over g_p rows (4096 elements). One CTA per row.
// 256 threads x 16 elements, register-resident, block reductions.
// ---------------------------------------------------------------------------
__global__ __launch_bounds__(256, 8)
void softmax_kernel() {
    const int row = blockIdx.x;
    const int b   = blockIdx.y;
    float* p = g_p + ((size_t)b * NN + row) * NN;

    const int tid = threadIdx.x;
    float4 v[4];
    #pragma unroll
    for (int i = 0; i < 4; i++)
        v[i] = *(const float4*)&p[tid * 16 + i * 4];

    // local max
    float m = v[0].x;
    #pragma unroll
    for (int i = 0; i < 4; i++) {
        m = fmaxf(m, v[i].x); m = fmaxf(m, v[i].y);
        m = fmaxf(m, v[i].z); m = fmaxf(m, v[i].w);
    }
    // block max reduce
    __shared__ float red[8];
    #pragma unroll
    for (int off = 16; off > 0; off >>= 1)
        m = fmaxf(m, __shfl_xor_sync(0xffffffffu, m, off));
    if ((tid & 31) == 0) red[tid >> 5] = m;
    __syncthreads();
    m = red[0];
    #pragma unroll
    for (int w = 1; w < 8; w++) m = fmaxf(m, red[w]);
    __syncthreads();

    // exp + local sum
    float s = 0.f;
    #pragma unroll
    for (int i = 0; i < 4; i++) {
        v[i].x = __expf(v[i].x - m); s += v[i].x;
        v[i].y = __expf(v[i].y - m); s += v[i].y;
        v[i].z = __expf(v[i].z - m); s += v[i].z;
        v[i].w = __expf(v[i].w - m); s += v[i].w;
    }
    #pragma unroll
    for (int off = 16; off > 0; off >>= 1)
        s += __shfl_xor_sync(0xffffffffu, s, off);
    if ((tid & 31) == 0) red[tid >> 5] = s;
    __syncthreads();
    s = 0.f;
    #pragma unroll
    for (int w = 0; w < 8; w++) s += red[w];
    const float inv = 1.0f / s;

    #pragma unroll
    for (int i = 0; i < 4; i++) {
        v[i].x *= inv; v[i].y *= inv; v[i].z *= inv; v[i].w *= inv;
        *(float4*)&p[tid * 16 + i * 4] = v[i];
    }
}

// ---------------------------------------------------------------------------
// Kernel 4: Out'[n][c] = sum_j P[b][n][j] * V'[j][c];  y = alpha*Out' + x.
// Output layout y[b][c][n] (matches x). Tile 64(c, ty) x 64(n, tx), K-tile 64.
// ---------------------------------------------------------------------------
__global__ __launch_bounds__(256, 4)
void pv_kernel(const float* __restrict__ x,
               const float* __restrict__ alpha,
               float* __restrict__ y) {
    const int n0 = blockIdx.x * 64;   // query/spatial index (tx side)
    const int c0 = blockIdx.y * 64;   // channel (ty side)
    const int b  = blockIdx.z;

    __shared__ float vs[64][65];  // [kk][cc]  (broadcast side)
    __shared__ float ps[64][68];  // [kk][nn]  (float4 side)

    const int tid = threadIdx.x;
    const int tx = tid & 15, ty = tid >> 4;

    const float* qkv_b = g_qkv + (size_t)b * NN * QKV;
    const float* p_b   = g_p + (size_t)b * NN * NN;

    float acc[4][4] = {};

    for (int j0 = 0; j0 < NN; j0 += 64) {
        #pragma unroll
        for (int idx = tid; idx < 4096; idx += 256) {
            int r = idx >> 6, kk = idx & 63;
            vs[r][kk & 63] = 0.f;   // placeholder to keep compiler from reordering oddly
        }
        // real loads (overwrite): vs direct, ps transposed
        #pragma unroll
        for (int idx = tid; idx < 4096; idx += 256) {
            int kk = idx >> 6, cc = idx & 63;
            vs[kk][cc] = qkv_b[(size_t)(j0 + kk) * QKV + 128 + c0 + cc];
        }
        #pragma unroll
        for (int idx = tid; idx < 4096; idx += 256) {
            int nn = idx >> 6, kk = idx & 63;
            ps[kk][nn] = p_b[(size_t)(n0 + nn) * NN + j0 + kk];
        }
        __syncthreads();
        #pragma unroll
        for (int kk = 0; kk < 64; kk++) {
            float a[4];
            #pragma unroll
            for (int i = 0; i < 4; i++) a[i] = vs[kk][ty * 4 + i];
            float4 b4 = *(const float4*)&ps[kk][tx * 4];
            float bv4[4] = {b4.x, b4.y, b4.z, b4.w};
            #pragma unroll
            for (int i = 0; i < 4; i++)
                #pragma unroll
                for (int j = 0; j < 4; j++)
                    acc[i][j] += a[i] * bv4[j];
        }
        __syncthreads();
    }

    const float al = __ldg(alpha);
    #pragma unroll
    for (int i = 0; i < 4; i++) {
        size_t base = ((size_t)b * CC + c0 + ty * 4 + i) * NN + n0 + tx * 4;
        float4 xv = *(const float4*)&x[base];
        float4 o;
        o.x = al * acc[i][0] + xv.x;
        o.y = al * acc[i][1] + xv.y;
        o.z = al * acc[i][2] + xv.z;
        o.w = al * acc[i][3] + xv.w;
        *(float4*)&y[base] = o;
    }
}

// ---------------------------------------------------------------------------
extern "C" void kernel_launch(void* const* d_in, const int* in_sizes, int n_in,
                              void* d_out, int out_size) {
    const float* x     = (const float*)d_in[0];
    const float* wq    = (const float*)d_in[1];
    const float* bq    = (const float*)d_in[2];
    const float* wk    = (const float*)d_in[3];
    const float* bk    = (const float*)d_in[4];
    const float* wv    = (const float*)d_in[5];
    const float* bv    = (const float*)d_in[6];
    const float* alpha = (const float*)d_in[7];
    float* y = (float*)d_out;

    dim3 blk(256);

    dim3 g1(NN / 64, QKV / 64, BB);        // 64 x 10 x 4
    proj_kernel<<<g1, blk>>>(x, wq, bq, wk, bk, wv, bv);

    dim3 g2(NN / 64, NN / 64, BB);         // 64 x 64 x 4
    logits_kernel<<<g2, blk>>>();

    dim3 g3(NN, BB);                       // one CTA per attn row
    softmax_kernel<<<g3, blk>>>();

    dim3 g4(NN / 64, CC / 64, BB);         // 64 x 8 x 4
    pv_kernel<<<g4, blk>>>(x, alpha, y);
}

// round 5
// speedup vs baseline: 2.4229x; 2.4229x over previous
#include <cuda_runtime.h>
#include <cuda_bf16.h>
#include <cstdint>

// Problem constants
#define BB   4
#define CC   512
#define NN   4096
#define MIDD 64

// ---------------------------------------------------------------------------
// Scratch (__device__ globals; allocation-free rule). Split-bf16: hi + lo.
// ---------------------------------------------------------------------------
__device__ __nv_bfloat16 g_qh[(size_t)BB * NN * MIDD];
__device__ __nv_bfloat16 g_ql[(size_t)BB * NN * MIDD];
__device__ __nv_bfloat16 g_kh[(size_t)BB * NN * MIDD];
__device__ __nv_bfloat16 g_kl[(size_t)BB * NN * MIDD];
__device__ __nv_bfloat16 g_vh[(size_t)BB * CC * NN];    // [b][c][n]
__device__ __nv_bfloat16 g_vl[(size_t)BB * CC * NN];
__device__ float         g_s[(size_t)BB * NN * NN];     // fp32 logits
__device__ __nv_bfloat16 g_ph[(size_t)BB * NN * NN];    // probs hi
__device__ __nv_bfloat16 g_pl[(size_t)BB * NN * NN];    // probs lo

static __device__ __forceinline__ uint32_t pack2(float a, float b) {
    __nv_bfloat162 t = __floats2bfloat162_rn(a, b);
    return *(uint32_t*)&t;
}
static __device__ __forceinline__ void split2(float a, float b, uint32_t& h, uint32_t& l) {
    __nv_bfloat16 ha = __float2bfloat16_rn(a);
    __nv_bfloat16 hb = __float2bfloat16_rn(b);
    __nv_bfloat16 la = __float2bfloat16_rn(a - __bfloat162float(ha));
    __nv_bfloat16 lb = __float2bfloat16_rn(b - __bfloat162float(hb));
    __nv_bfloat162 th; th.x = ha; th.y = hb;
    __nv_bfloat162 tl; tl.x = la; tl.y = lb;
    h = *(uint32_t*)&th;  l = *(uint32_t*)&tl;
}

#define MMA_BF16(d, a, b)                                                     \
    asm volatile(                                                             \
        "mma.sync.aligned.m16n8k16.row.col.f32.bf16.bf16.f32 "                \
        "{%0,%1,%2,%3}, {%4,%5,%6,%7}, {%8,%9}, {%0,%1,%2,%3};"               \
        : "+f"(d[0]), "+f"(d[1]), "+f"(d[2]), "+f"(d[3])                      \
        : "r"(a[0]), "r"(a[1]), "r"(a[2]), "r"(a[3]), "r"(b[0]), "r"(b[1]))

static __device__ __forceinline__ void cp16(uint32_t s, const void* g) {
    asm volatile("cp.async.cg.shared.global [%0], [%1], 16;\n" :: "r"(s), "l"(g) : "memory");
}

// ---------------------------------------------------------------------------
// Kernel 1: fused QKV projection (fp32 compute, split-bf16 outputs).
// ---------------------------------------------------------------------------
__global__ __launch_bounds__(256, 4)
void proj_kernel(const float* __restrict__ x,
                 const float* __restrict__ wq, const float* __restrict__ bq,
                 const float* __restrict__ wk, const float* __restrict__ bk,
                 const float* __restrict__ wv, const float* __restrict__ bv) {
    const int n0 = blockIdx.x * 64;
    const int m0 = blockIdx.y * 64;
    const int b  = blockIdx.z;

    const float* W;  const float* bias;  int wr0;
    if (m0 < 64)        { W = wq; bias = bq; wr0 = m0; }
    else if (m0 < 128)  { W = wk; bias = bk; wr0 = m0 - 64; }
    else                { W = wv; bias = bv; wr0 = m0 - 128; }

    __shared__ float xs[16][68];
    __shared__ float ws[16][68];

    const int tid = threadIdx.x;
    const int tx = tid & 15, ty = tid >> 4;

    float acc[4][4] = {};
    const float* xb = x + (size_t)b * CC * NN;

    for (int c0 = 0; c0 < CC; c0 += 16) {
        #pragma unroll
        for (int i = tid; i < 1024; i += 256) {
            int kk = i >> 6, nn = i & 63;
            xs[kk][nn] = xb[(size_t)(c0 + kk) * NN + n0 + nn];
        }
        #pragma unroll
        for (int i = tid; i < 1024; i += 256) {
            int kk = i & 15, mm = i >> 4;
            ws[kk][mm] = W[(wr0 + mm) * CC + c0 + kk];
        }
        __syncthreads();
        #pragma unroll
        for (int kk = 0; kk < 16; kk++) {
            float4 a4 = *(const float4*)&xs[kk][ty * 4];
            float4 b4 = *(const float4*)&ws[kk][tx * 4];
            float a[4] = {a4.x, a4.y, a4.z, a4.w};
            float bb[4] = {b4.x, b4.y, b4.z, b4.w};
            #pragma unroll
            for (int i = 0; i < 4; i++)
                #pragma unroll
                for (int j = 0; j < 4; j++)
                    acc[i][j] += a[i] * bb[j];
        }
        __syncthreads();
    }

    float bs[4];
    #pragma unroll
    for (int j = 0; j < 4; j++) bs[j] = bias[wr0 + tx * 4 + j];

    if (m0 < 128) {
        __nv_bfloat16* dh = (m0 < 64) ? g_qh : g_kh;
        __nv_bfloat16* dl = (m0 < 64) ? g_ql : g_kl;
        #pragma unroll
        for (int i = 0; i < 4; i++) {
            uint2 uh, ul;
            split2(acc[i][0] + bs[0], acc[i][1] + bs[1], uh.x, ul.x);
            split2(acc[i][2] + bs[2], acc[i][3] + bs[3], uh.y, ul.y);
            size_t off = ((size_t)b * NN + n0 + ty * 4 + i) * MIDD + tx * 4;
            *(uint2*)&dh[off] = uh;
            *(uint2*)&dl[off] = ul;
        }
    } else {
        #pragma unroll
        for (int j = 0; j < 4; j++) {
            int c = m0 - 128 + tx * 4 + j;
            float bj = bs[j];
            uint2 uh, ul;
            split2(acc[0][j] + bj, acc[1][j] + bj, uh.x, ul.x);
            split2(acc[2][j] + bj, acc[3][j] + bj, uh.y, ul.y);
            size_t off = ((size_t)b * CC + c) * NN + n0 + ty * 4;
            *(uint2*)&g_vh[off] = uh;
            *(uint2*)&g_vl[off] = ul;
        }
    }
}

// ---------------------------------------------------------------------------
// Kernel 2: logits via split-bf16 HMMA (3 passes). S[i][j]=sum_m Q[i][m]K[j][m].
// Tile 128x128, 8 warps, per-warp 64x32.
// ---------------------------------------------------------------------------
#define LSTR 72
#define LOGITS_SMEM (4 * 128 * LSTR * 2)

__global__ __launch_bounds__(256)
void logits_kernel() {
    const int j0 = blockIdx.x * 128;
    const int i0 = blockIdx.y * 128;
    const int b  = blockIdx.z;

    extern __shared__ __align__(16) __nv_bfloat16 lsm[];
    __nv_bfloat16* sQh = lsm;
    __nv_bfloat16* sQl = lsm + 128 * LSTR;
    __nv_bfloat16* sKh = lsm + 2 * 128 * LSTR;
    __nv_bfloat16* sKl = lsm + 3 * 128 * LSTR;

    const int tid = threadIdx.x;
    const int wid = tid >> 5, lane = tid & 31;
    const int wm = wid >> 2, wn = wid & 3;
    const int g = lane >> 2, c = lane & 3;

    const size_t qoff = (size_t)b * NN * MIDD;

    #pragma unroll
    for (int i = tid; i < 1024; i += 256) {   // 128 rows x 8 chunks of 8 halves
        int r = i >> 3, c8 = i & 7;
        size_t go = qoff + (size_t)(i0 + r) * MIDD + c8 * 8;
        size_t ko = qoff + (size_t)(j0 + r) * MIDD + c8 * 8;
        int so = r * LSTR + c8 * 8;
        *(uint4*)&sQh[so] = *(const uint4*)&g_qh[go];
        *(uint4*)&sQl[so] = *(const uint4*)&g_ql[go];
        *(uint4*)&sKh[so] = *(const uint4*)&g_kh[ko];
        *(uint4*)&sKl[so] = *(const uint4*)&g_kl[ko];
    }
    __syncthreads();

    float acc[4][4][4] = {};

    #pragma unroll
    for (int kc = 0; kc < 4; kc++) {
        uint32_t afh[4][4], afl[4][4], bfh[4][2], bfl[4][2];
        #pragma unroll
        for (int mi = 0; mi < 4; mi++) {
            int o = (wm * 64 + mi * 16 + g) * LSTR + kc * 16 + 2 * c;
            afh[mi][0] = *(const uint32_t*)&sQh[o];
            afh[mi][1] = *(const uint32_t*)&sQh[o + 8 * LSTR];
            afh[mi][2] = *(const uint32_t*)&sQh[o + 8];
            afh[mi][3] = *(const uint32_t*)&sQh[o + 8 * LSTR + 8];
            afl[mi][0] = *(const uint32_t*)&sQl[o];
            afl[mi][1] = *(const uint32_t*)&sQl[o + 8 * LSTR];
            afl[mi][2] = *(const uint32_t*)&sQl[o + 8];
            afl[mi][3] = *(const uint32_t*)&sQl[o + 8 * LSTR + 8];
        }
        #pragma unroll
        for (int ni = 0; ni < 4; ni++) {
            int o = (wn * 32 + ni * 8 + g) * LSTR + kc * 16 + 2 * c;
            bfh[ni][0] = *(const uint32_t*)&sKh[o];
            bfh[ni][1] = *(const uint32_t*)&sKh[o + 8];
            bfl[ni][0] = *(const uint32_t*)&sKl[o];
            bfl[ni][1] = *(const uint32_t*)&sKl[o + 8];
        }
        #pragma unroll
        for (int mi = 0; mi < 4; mi++)
            #pragma unroll
            for (int ni = 0; ni < 4; ni++) {
                MMA_BF16(acc[mi][ni], afh[mi], bfh[ni]);
                MMA_BF16(acc[mi][ni], afh[mi], bfl[ni]);
                MMA_BF16(acc[mi][ni], afl[mi], bfh[ni]);
            }
    }

    float* sb = g_s + ((size_t)b * NN + i0) * NN + j0;
    #pragma unroll
    for (int mi = 0; mi < 4; mi++)
        #pragma unroll
        for (int ni = 0; ni < 4; ni++) {
            int r = wm * 64 + mi * 16 + g;
            int cn = wn * 32 + ni * 8 + 2 * c;
            float2 v0 = {acc[mi][ni][0], acc[mi][ni][1]};
            float2 v1 = {acc[mi][ni][2], acc[mi][ni][3]};
            *(float2*)&sb[(size_t)r * NN + cn] = v0;
            *(float2*)&sb[(size_t)(r + 8) * NN + cn] = v1;
        }
}

// ---------------------------------------------------------------------------
// Kernel 3: row softmax. Reads fp32 logits, writes split-bf16 probs.
// ---------------------------------------------------------------------------
__global__ __launch_bounds__(256, 8)
void softmax_kernel() {
    const int row = blockIdx.x;
    const int b   = blockIdx.y;
    const float* s = g_s + ((size_t)b * NN + row) * NN;
    __nv_bfloat16* ph = g_ph + ((size_t)b * NN + row) * NN;
    __nv_bfloat16* pl = g_pl + ((size_t)b * NN + row) * NN;

    const int tid = threadIdx.x;
    float4 v[4];
    #pragma unroll
    for (int i = 0; i < 4; i++)
        v[i] = *(const float4*)&s[tid * 16 + i * 4];

    float m = v[0].x;
    #pragma unroll
    for (int i = 0; i < 4; i++) {
        m = fmaxf(m, v[i].x); m = fmaxf(m, v[i].y);
        m = fmaxf(m, v[i].z); m = fmaxf(m, v[i].w);
    }
    __shared__ float red[8];
    #pragma unroll
    for (int off = 16; off > 0; off >>= 1)
        m = fmaxf(m, __shfl_xor_sync(0xffffffffu, m, off));
    if ((tid & 31) == 0) red[tid >> 5] = m;
    __syncthreads();
    m = red[0];
    #pragma unroll
    for (int w = 1; w < 8; w++) m = fmaxf(m, red[w]);
    __syncthreads();

    float sum = 0.f;
    #pragma unroll
    for (int i = 0; i < 4; i++) {
        v[i].x = __expf(v[i].x - m); sum += v[i].x;
        v[i].y = __expf(v[i].y - m); sum += v[i].y;
        v[i].z = __expf(v[i].z - m); sum += v[i].z;
        v[i].w = __expf(v[i].w - m); sum += v[i].w;
    }
    #pragma unroll
    for (int off = 16; off > 0; off >>= 1)
        sum += __shfl_xor_sync(0xffffffffu, sum, off);
    if ((tid & 31) == 0) red[tid >> 5] = sum;
    __syncthreads();
    sum = 0.f;
    #pragma unroll
    for (int w = 0; w < 8; w++) sum += red[w];
    const float inv = 1.0f / sum;

    uint32_t hh[8], ll[8];
    #pragma unroll
    for (int i = 0; i < 4; i++) {
        split2(v[i].x * inv, v[i].y * inv, hh[2 * i],     ll[2 * i]);
        split2(v[i].z * inv, v[i].w * inv, hh[2 * i + 1], ll[2 * i + 1]);
    }
    uint4 u;
    u = make_uint4(hh[0], hh[1], hh[2], hh[3]); *(uint4*)&ph[tid * 16] = u;
    u = make_uint4(hh[4], hh[5], hh[6], hh[7]); *(uint4*)&ph[tid * 16 + 8] = u;
    u = make_uint4(ll[0], ll[1], ll[2], ll[3]); *(uint4*)&pl[tid * 16] = u;
    u = make_uint4(ll[4], ll[5], ll[6], ll[7]); *(uint4*)&pl[tid * 16 + 8] = u;
}

// ---------------------------------------------------------------------------
// Kernel 4: PV via split-bf16 HMMA (3 passes) + cp.async double buffering.
// Out^T[c][n] = sum_j V[c][j] * P[n][j];  y[b][c][n] = alpha*Out + x.
// Tile c=128 x n=128, k-tile 32.
// ---------------------------------------------------------------------------
#define PSTR 40
#define PV_TILE  (128 * PSTR)            // halves per stream tile
#define PV_STAGE (4 * PV_TILE)           // 4 streams per stage
#define PV_SMEM  (2 * PV_STAGE * 2)      // bytes

__global__ __launch_bounds__(256)
void pv_kernel(const float* __restrict__ x,
               const float* __restrict__ alpha,
               float* __restrict__ y) {
    const int n0 = blockIdx.x * 128;
    const int c0 = blockIdx.y * 128;
    const int b  = blockIdx.z;

    extern __shared__ __align__(16) __nv_bfloat16 psm[];

    const int tid = threadIdx.x;
    const int wid = tid >> 5, lane = tid & 31;
    const int wm = wid >> 2, wn = wid & 3;
    const int g = lane >> 2, c = lane & 3;

    const uint32_t sbase = (uint32_t)__cvta_generic_to_shared(psm);

    const __nv_bfloat16* vh = g_vh + (size_t)(b * CC + c0) * NN;
    const __nv_bfloat16* vl = g_vl + (size_t)(b * CC + c0) * NN;
    const __nv_bfloat16* ph = g_ph + ((size_t)b * NN + n0) * NN;
    const __nv_bfloat16* pl = g_pl + ((size_t)b * NN + n0) * NN;

    const int lr  = tid >> 1;            // 0..127
    const int lc0 = (tid & 1) * 2;       // chunk base (0 or 2), chunks of 8 halves

    // prologue: tile 0 into stage 0
    #pragma unroll
    for (int q = 0; q < 2; q++) {
        int c8 = lc0 + q;
        uint32_t so = lr * (PSTR * 2) + c8 * 16;
        size_t go = (size_t)lr * NN + c8 * 8;
        cp16(sbase + so,                      &vh[go]);
        cp16(sbase + PV_TILE * 2 + so,        &vl[go]);
        cp16(sbase + 2 * PV_TILE * 2 + so,    &ph[go]);
        cp16(sbase + 3 * PV_TILE * 2 + so,    &pl[go]);
    }
    asm volatile("cp.async.commit_group;\n" ::: "memory");

    float acc[4][4][4] = {};

    for (int jt = 0; jt < NN / 32; jt++) {
        if (jt + 1 < NN / 32) {
            int j1 = (jt + 1) * 32;
            uint32_t dofs = ((jt + 1) & 1) ? (uint32_t)(PV_STAGE * 2) : 0u;
            #pragma unroll
            for (int q = 0; q < 2; q++) {
                int c8 = lc0 + q;
                uint32_t so = dofs + lr * (PSTR * 2) + c8 * 16;
                size_t go = (size_t)lr * NN + j1 + c8 * 8;
                cp16(sbase + so,                   &vh[go]);
                cp16(sbase + PV_TILE * 2 + so,     &vl[go]);
                cp16(sbase + 2 * PV_TILE * 2 + so, &ph[go]);
                cp16(sbase + 3 * PV_TILE * 2 + so, &pl[go]);
            }
            asm volatile("cp.async.commit_group;\n" ::: "memory");
            asm volatile("cp.async.wait_group 1;\n" ::: "memory");
        } else {
            asm volatile("cp.async.wait_group 0;\n" ::: "memory");
        }
        __syncthreads();

        const __nv_bfloat16* Vh = psm + (jt & 1) * PV_STAGE;
        const __nv_bfloat16* Vl = Vh + PV_TILE;
        const __nv_bfloat16* Ph = Vh + 2 * PV_TILE;
        const __nv_bfloat16* Pl = Vh + 3 * PV_TILE;

        #pragma unroll
        for (int kc = 0; kc < 2; kc++) {
            uint32_t afh[4][4], afl[4][4], bfh[4][2], bfl[4][2];
            #pragma unroll
            for (int mi = 0; mi < 4; mi++) {
                int o = (wm * 64 + mi * 16 + g) * PSTR + kc * 16 + 2 * c;
                afh[mi][0] = *(const uint32_t*)&Vh[o];
                afh[mi][1] = *(const uint32_t*)&Vh[o + 8 * PSTR];
                afh[mi][2] = *(const uint32_t*)&Vh[o + 8];
                afh[mi][3] = *(const uint32_t*)&Vh[o + 8 * PSTR + 8];
                afl[mi][0] = *(const uint32_t*)&Vl[o];
                afl[mi][1] = *(const uint32_t*)&Vl[o + 8 * PSTR];
                afl[mi][2] = *(const uint32_t*)&Vl[o + 8];
                afl[mi][3] = *(const uint32_t*)&Vl[o + 8 * PSTR + 8];
            }
            #pragma unroll
            for (int ni = 0; ni < 4; ni++) {
                int o = (wn * 32 + ni * 8 + g) * PSTR + kc * 16 + 2 * c;
                bfh[ni][0] = *(const uint32_t*)&Ph[o];
                bfh[ni][1] = *(const uint32_t*)&Ph[o + 8];
                bfl[ni][0] = *(const uint32_t*)&Pl[o];
                bfl[ni][1] = *(const uint32_t*)&Pl[o + 8];
            }
            #pragma unroll
            for (int mi = 0; mi < 4; mi++)
                #pragma unroll
                for (int ni = 0; ni < 4; ni++) {
                    MMA_BF16(acc[mi][ni], afh[mi], bfh[ni]);
                    MMA_BF16(acc[mi][ni], afh[mi], bfl[ni]);
                    MMA_BF16(acc[mi][ni], afl[mi], bfh[ni]);
                }
        }
        __syncthreads();
    }

    const float al = __ldg(alpha);
    #pragma unroll
    for (int mi = 0; mi < 4; mi++)
        #pragma unroll
        for (int ni = 0; ni < 4; ni++) {
            int cc = c0 + wm * 64 + mi * 16 + g;
            int nn = n0 + wn * 32 + ni * 8 + 2 * c;
            size_t o0 = ((size_t)b * CC + cc) * NN + nn;
            float2 xv = *(const float2*)&x[o0];
            float2 o;
            o.x = al * acc[mi][ni][0] + xv.x;
            o.y = al * acc[mi][ni][1] + xv.y;
            *(float2*)&y[o0] = o;
            size_t o1 = o0 + (size_t)8 * NN;
            xv = *(const float2*)&x[o1];
            o.x = al * acc[mi][ni][2] + xv.x;
            o.y = al * acc[mi][ni][3] + xv.y;
            *(float2*)&y[o1] = o;
        }
}

// ---------------------------------------------------------------------------
extern "C" void kernel_launch(void* const* d_in, const int* in_sizes, int n_in,
                              void* d_out, int out_size) {
    const float* x     = (const float*)d_in[0];
    const float* wq    = (const float*)d_in[1];
    const float* bq    = (const float*)d_in[2];
    const float* wk    = (const float*)d_in[3];
    const float* bk    = (const float*)d_in[4];
    const float* wv    = (const float*)d_in[5];
    const float* bv    = (const float*)d_in[6];
    const float* alpha = (const float*)d_in[7];
    float* y = (float*)d_out;

    cudaFuncSetAttribute(logits_kernel,
                         cudaFuncAttributeMaxDynamicSharedMemorySize, LOGITS_SMEM);
    cudaFuncSetAttribute(pv_kernel,
                         cudaFuncAttributeMaxDynamicSharedMemorySize, PV_SMEM);

    dim3 blk(256);

    dim3 g1(NN / 64, 640 / 64, BB);
    proj_kernel<<<g1, blk>>>(x, wq, bq, wk, bk, wv, bv);

    dim3 g2(NN / 128, NN / 128, BB);
    logits_kernel<<<g2, blk, LOGITS_SMEM>>>();

    dim3 g3(NN, BB);
    softmax_kernel<<<g3, blk>>>();

    dim3 g4(NN / 128, CC / 128, BB);
    pv_kernel<<<g4, blk, PV_SMEM>>>(x, alpha, y);
}

// round 11
// speedup vs baseline: 3.7660x; 1.5543x over previous
#include <cuda_runtime.h>
#include <cuda_bf16.h>
#include <cuda_fp16.h>
#include <cstdint>

// Problem constants
#define BB   4
#define CC   512
#define NN   4096
#define MIDD 64

// ---------------------------------------------------------------------------
// Scratch (__device__ globals; allocation-free rule).
// q/k: split-bf16 (accuracy-critical through softmax). V/P: single fp16.
// ---------------------------------------------------------------------------
__device__ __nv_bfloat16 g_qh[(size_t)BB * NN * MIDD];
__device__ __nv_bfloat16 g_ql[(size_t)BB * NN * MIDD];
__device__ __nv_bfloat16 g_kh[(size_t)BB * NN * MIDD];
__device__ __nv_bfloat16 g_kl[(size_t)BB * NN * MIDD];
__device__ __half        g_v[(size_t)BB * CC * NN];     // [b][c][n]
__device__ float         g_s[(size_t)BB * NN * NN];     // fp32 logits
__device__ __half        g_p[(size_t)BB * NN * NN];     // fp16 probs

static __device__ __forceinline__ void split2(float a, float b, uint32_t& h, uint32_t& l) {
    __nv_bfloat16 ha = __float2bfloat16_rn(a);
    __nv_bfloat16 hb = __float2bfloat16_rn(b);
    __nv_bfloat16 la = __float2bfloat16_rn(a - __bfloat162float(ha));
    __nv_bfloat16 lb = __float2bfloat16_rn(b - __bfloat162float(hb));
    __nv_bfloat162 th; th.x = ha; th.y = hb;
    __nv_bfloat162 tl; tl.x = la; tl.y = lb;
    h = *(uint32_t*)&th;  l = *(uint32_t*)&tl;
}
static __device__ __forceinline__ uint32_t packh2(float a, float b) {
    __half2 t = __floats2half2_rn(a, b);
    return *(uint32_t*)&t;
}

#define MMA_BF16(d, a, b)                                                     \
    asm volatile(                                                             \
        "mma.sync.aligned.m16n8k16.row.col.f32.bf16.bf16.f32 "                \
        "{%0,%1,%2,%3}, {%4,%5,%6,%7}, {%8,%9}, {%0,%1,%2,%3};"               \
        : "+f"(d[0]), "+f"(d[1]), "+f"(d[2]), "+f"(d[3])                      \
        : "r"(a[0]), "r"(a[1]), "r"(a[2]), "r"(a[3]), "r"(b[0]), "r"(b[1]))

#define MMA_F16(d, a, b)                                                      \
    asm volatile(                                                             \
        "mma.sync.aligned.m16n8k16.row.col.f32.f16.f16.f32 "                  \
        "{%0,%1,%2,%3}, {%4,%5,%6,%7}, {%8,%9}, {%0,%1,%2,%3};"               \
        : "+f"(d[0]), "+f"(d[1]), "+f"(d[2]), "+f"(d[3])                      \
        : "r"(a[0]), "r"(a[1]), "r"(a[2]), "r"(a[3]), "r"(b[0]), "r"(b[1]))

static __device__ __forceinline__ void cp16(uint32_t s, const void* g) {
    asm volatile("cp.async.cg.shared.global [%0], [%1], 16;\n" :: "r"(s), "l"(g) : "memory");
}

// ---------------------------------------------------------------------------
// Kernel 1: fused QKV projection (fp32 compute; split-bf16 q/k, fp16 v).
// ---------------------------------------------------------------------------
__global__ __launch_bounds__(256, 4)
void proj_kernel(const float* __restrict__ x,
                 const float* __restrict__ wq, const float* __restrict__ bq,
                 const float* __restrict__ wk, const float* __restrict__ bk,
                 const float* __restrict__ wv, const float* __restrict__ bv) {
    const int n0 = blockIdx.x * 64;
    const int m0 = blockIdx.y * 64;
    const int b  = blockIdx.z;

    const float* W;  const float* bias;  int wr0;
    if (m0 < 64)        { W = wq; bias = bq; wr0 = m0; }
    else if (m0 < 128)  { W = wk; bias = bk; wr0 = m0 - 64; }
    else                { W = wv; bias = bv; wr0 = m0 - 128; }

    __shared__ float xs[16][68];
    __shared__ float ws[16][68];

    const int tid = threadIdx.x;
    const int tx = tid & 15, ty = tid >> 4;

    float acc[4][4] = {};
    const float* xb = x + (size_t)b * CC * NN;

    for (int c0 = 0; c0 < CC; c0 += 16) {
        #pragma unroll
        for (int i = tid; i < 1024; i += 256) {
            int kk = i >> 6, nn = i & 63;
            xs[kk][nn] = xb[(size_t)(c0 + kk) * NN + n0 + nn];
        }
        #pragma unroll
        for (int i = tid; i < 1024; i += 256) {
            int kk = i & 15, mm = i >> 4;
            ws[kk][mm] = W[(wr0 + mm) * CC + c0 + kk];
        }
        __syncthreads();
        #pragma unroll
        for (int kk = 0; kk < 16; kk++) {
            float4 a4 = *(const float4*)&xs[kk][ty * 4];
            float4 b4 = *(const float4*)&ws[kk][tx * 4];
            float a[4] = {a4.x, a4.y, a4.z, a4.w};
            float bb[4] = {b4.x, b4.y, b4.z, b4.w};
            #pragma unroll
            for (int i = 0; i < 4; i++)
                #pragma unroll
                for (int j = 0; j < 4; j++)
                    acc[i][j] += a[i] * bb[j];
        }
        __syncthreads();
    }

    float bs[4];
    #pragma unroll
    for (int j = 0; j < 4; j++) bs[j] = bias[wr0 + tx * 4 + j];

    if (m0 < 128) {
        __nv_bfloat16* dh = (m0 < 64) ? g_qh : g_kh;
        __nv_bfloat16* dl = (m0 < 64) ? g_ql : g_kl;
        #pragma unroll
        for (int i = 0; i < 4; i++) {
            uint2 uh, ul;
            split2(acc[i][0] + bs[0], acc[i][1] + bs[1], uh.x, ul.x);
            split2(acc[i][2] + bs[2], acc[i][3] + bs[3], uh.y, ul.y);
            size_t off = ((size_t)b * NN + n0 + ty * 4 + i) * MIDD + tx * 4;
            *(uint2*)&dh[off] = uh;
            *(uint2*)&dl[off] = ul;
        }
    } else {
        #pragma unroll
        for (int j = 0; j < 4; j++) {
            int c = m0 - 128 + tx * 4 + j;
            float bj = bs[j];
            uint2 u;
            u.x = packh2(acc[0][j] + bj, acc[1][j] + bj);
            u.y = packh2(acc[2][j] + bj, acc[3][j] + bj);
            size_t off = ((size_t)b * CC + c) * NN + n0 + ty * 4;
            *(uint2*)&g_v[off] = u;
        }
    }
}

// ---------------------------------------------------------------------------
// Kernel 2: logits via split-bf16 HMMA (3 passes). S[i][j]=sum_m Q[i][m]K[j][m].
// ---------------------------------------------------------------------------
#define LSTR 72
#define LOGITS_SMEM (4 * 128 * LSTR * 2)

__global__ __launch_bounds__(256)
void logits_kernel() {
    const int j0 = blockIdx.x * 128;
    const int i0 = blockIdx.y * 128;
    const int b  = blockIdx.z;

    extern __shared__ __align__(16) __nv_bfloat16 lsm[];
    __nv_bfloat16* sQh = lsm;
    __nv_bfloat16* sQl = lsm + 128 * LSTR;
    __nv_bfloat16* sKh = lsm + 2 * 128 * LSTR;
    __nv_bfloat16* sKl = lsm + 3 * 128 * LSTR;

    const int tid = threadIdx.x;
    const int wid = tid >> 5, lane = tid & 31;
    const int wm = wid >> 2, wn = wid & 3;
    const int g = lane >> 2, c = lane & 3;

    const size_t qoff = (size_t)b * NN * MIDD;

    #pragma unroll
    for (int i = tid; i < 1024; i += 256) {
        int r = i >> 3, c8 = i & 7;
        size_t go = qoff + (size_t)(i0 + r) * MIDD + c8 * 8;
        size_t ko = qoff + (size_t)(j0 + r) * MIDD + c8 * 8;
        int so = r * LSTR + c8 * 8;
        *(uint4*)&sQh[so] = *(const uint4*)&g_qh[go];
        *(uint4*)&sQl[so] = *(const uint4*)&g_ql[go];
        *(uint4*)&sKh[so] = *(const uint4*)&g_kh[ko];
        *(uint4*)&sKl[so] = *(const uint4*)&g_kl[ko];
    }
    __syncthreads();

    float acc[4][4][4] = {};

    #pragma unroll
    for (int kc = 0; kc < 4; kc++) {
        uint32_t afh[4][4], afl[4][4], bfh[4][2], bfl[4][2];
        #pragma unroll
        for (int mi = 0; mi < 4; mi++) {
            int o = (wm * 64 + mi * 16 + g) * LSTR + kc * 16 + 2 * c;
            afh[mi][0] = *(const uint32_t*)&sQh[o];
            afh[mi][1] = *(const uint32_t*)&sQh[o + 8 * LSTR];
            afh[mi][2] = *(const uint32_t*)&sQh[o + 8];
            afh[mi][3] = *(const uint32_t*)&sQh[o + 8 * LSTR + 8];
            afl[mi][0] = *(const uint32_t*)&sQl[o];
            afl[mi][1] = *(const uint32_t*)&sQl[o + 8 * LSTR];
            afl[mi][2] = *(const uint32_t*)&sQl[o + 8];
            afl[mi][3] = *(const uint32_t*)&sQl[o + 8 * LSTR + 8];
        }
        #pragma unroll
        for (int ni = 0; ni < 4; ni++) {
            int o = (wn * 32 + ni * 8 + g) * LSTR + kc * 16 + 2 * c;
            bfh[ni][0] = *(const uint32_t*)&sKh[o];
            bfh[ni][1] = *(const uint32_t*)&sKh[o + 8];
            bfl[ni][0] = *(const uint32_t*)&sKl[o];
            bfl[ni][1] = *(const uint32_t*)&sKl[o + 8];
        }
        #pragma unroll
        for (int mi = 0; mi < 4; mi++)
            #pragma unroll
            for (int ni = 0; ni < 4; ni++) {
                MMA_BF16(acc[mi][ni], afh[mi], bfh[ni]);
                MMA_BF16(acc[mi][ni], afh[mi], bfl[ni]);
                MMA_BF16(acc[mi][ni], afl[mi], bfh[ni]);
            }
    }

    float* sb = g_s + ((size_t)b * NN + i0) * NN + j0;
    #pragma unroll
    for (int mi = 0; mi < 4; mi++)
        #pragma unroll
        for (int ni = 0; ni < 4; ni++) {
            int r = wm * 64 + mi * 16 + g;
            int cn = wn * 32 + ni * 8 + 2 * c;
            float2 v0 = {acc[mi][ni][0], acc[mi][ni][1]};
            float2 v1 = {acc[mi][ni][2], acc[mi][ni][3]};
            *(float2*)&sb[(size_t)r * NN + cn] = v0;
            *(float2*)&sb[(size_t)(r + 8) * NN + cn] = v1;
        }
}

// ---------------------------------------------------------------------------
// Kernel 3: row softmax. Reads fp32 logits, writes fp16 probs.
// ---------------------------------------------------------------------------
__global__ __launch_bounds__(256, 8)
void softmax_kernel() {
    const int row = blockIdx.x;
    const int b   = blockIdx.y;
    const float* s = g_s + ((size_t)b * NN + row) * NN;
    __half* p = g_p + ((size_t)b * NN + row) * NN;

    const int tid = threadIdx.x;
    float4 v[4];
    #pragma unroll
    for (int i = 0; i < 4; i++)
        v[i] = *(const float4*)&s[tid * 16 + i * 4];

    float m = v[0].x;
    #pragma unroll
    for (int i = 0; i < 4; i++) {
        m = fmaxf(m, v[i].x); m = fmaxf(m, v[i].y);
        m = fmaxf(m, v[i].z); m = fmaxf(m, v[i].w);
    }
    __shared__ float red[8];
    #pragma unroll
    for (int off = 16; off > 0; off >>= 1)
        m = fmaxf(m, __shfl_xor_sync(0xffffffffu, m, off));
    if ((tid & 31) == 0) red[tid >> 5] = m;
    __syncthreads();
    m = red[0];
    #pragma unroll
    for (int w = 1; w < 8; w++) m = fmaxf(m, red[w]);
    __syncthreads();

    float sum = 0.f;
    #pragma unroll
    for (int i = 0; i < 4; i++) {
        v[i].x = __expf(v[i].x - m); sum += v[i].x;
        v[i].y = __expf(v[i].y - m); sum += v[i].y;
        v[i].z = __expf(v[i].z - m); sum += v[i].z;
        v[i].w = __expf(v[i].w - m); sum += v[i].w;
    }
    #pragma unroll
    for (int off = 16; off > 0; off >>= 1)
        sum += __shfl_xor_sync(0xffffffffu, sum, off);
    if ((tid & 31) == 0) red[tid >> 5] = sum;
    __syncthreads();
    sum = 0.f;
    #pragma unroll
    for (int w = 0; w < 8; w++) sum += red[w];
    const float inv = 1.0f / sum;

    uint32_t hh[8];
    #pragma unroll
    for (int i = 0; i < 4; i++) {
        hh[2 * i]     = packh2(v[i].x * inv, v[i].y * inv);
        hh[2 * i + 1] = packh2(v[i].z * inv, v[i].w * inv);
    }
    uint4 u;
    u = make_uint4(hh[0], hh[1], hh[2], hh[3]); *(uint4*)&p[tid * 16] = u;
    u = make_uint4(hh[4], hh[5], hh[6], hh[7]); *(uint4*)&p[tid * 16 + 8] = u;
}

// ---------------------------------------------------------------------------
// Kernel 4: PV via fp16 HMMA (single pass) + cp.async double buffering.
// Out^T[c][n] = sum_j V[c][j] * P[n][j];  y[b][c][n] = alpha*Out + x.
// Tile c=128 x n=128, k-tile 32.
// ---------------------------------------------------------------------------
#define PSTR 40
#define PV_TILE  (128 * PSTR)            // halves per stream tile
#define PV_STAGE (2 * PV_TILE)           // 2 streams per stage
#define PV_SMEM  (2 * PV_STAGE * 2)      // bytes (double buffered)

__global__ __launch_bounds__(256)
void pv_kernel(const float* __restrict__ x,
               const float* __restrict__ alpha,
               float* __restrict__ y) {
    const int n0 = blockIdx.x * 128;
    const int c0 = blockIdx.y * 128;
    const int b  = blockIdx.z;

    extern __shared__ __align__(16) __half psm[];

    const int tid = threadIdx.x;
    const int wid = tid >> 5, lane = tid & 31;
    const int wm = wid >> 2, wn = wid & 3;
    const int g = lane >> 2, c = lane & 3;

    const uint32_t sbase = (uint32_t)__cvta_generic_to_shared(psm);

    const __half* vv = g_v + (size_t)(b * CC + c0) * NN;
    const __half* pp = g_p + ((size_t)b * NN + n0) * NN;

    const int lr  = tid >> 1;            // 0..127
    const int lc0 = (tid & 1) * 2;       // chunk base (0 or 2), chunks of 8 halves

    // prologue: tile 0 into stage 0
    #pragma unroll
    for (int q = 0; q < 2; q++) {
        int c8 = lc0 + q;
        uint32_t so = lr * (PSTR * 2) + c8 * 16;
        size_t go = (size_t)lr * NN + c8 * 8;
        cp16(sbase + so,               &vv[go]);
        cp16(sbase + PV_TILE * 2 + so, &pp[go]);
    }
    asm volatile("cp.async.commit_group;\n" ::: "memory");

    float acc[4][4][4] = {};

    for (int jt = 0; jt < NN / 32; jt++) {
        if (jt + 1 < NN / 32) {
            int j1 = (jt + 1) * 32;
            uint32_t dofs = ((jt + 1) & 1) ? (uint32_t)(PV_STAGE * 2) : 0u;
            #pragma unroll
            for (int q = 0; q < 2; q++) {
                int c8 = lc0 + q;
                uint32_t so = dofs + lr * (PSTR * 2) + c8 * 16;
                size_t go = (size_t)lr * NN + j1 + c8 * 8;
                cp16(sbase + so,               &vv[go]);
                cp16(sbase + PV_TILE * 2 + so, &pp[go]);
            }
            asm volatile("cp.async.commit_group;\n" ::: "memory");
            asm volatile("cp.async.wait_group 1;\n" ::: "memory");
        } else {
            asm volatile("cp.async.wait_group 0;\n" ::: "memory");
        }
        __syncthreads();

        const __half* Vt = psm + (jt & 1) * PV_STAGE;
        const __half* Pt = Vt + PV_TILE;

        #pragma unroll
        for (int kc = 0; kc < 2; kc++) {
            uint32_t af[4][4], bf[4][2];
            #pragma unroll
            for (int mi = 0; mi < 4; mi++) {
                int o = (wm * 64 + mi * 16 + g) * PSTR + kc * 16 + 2 * c;
                af[mi][0] = *(const uint32_t*)&Vt[o];
                af[mi][1] = *(const uint32_t*)&Vt[o + 8 * PSTR];
                af[mi][2] = *(const uint32_t*)&Vt[o + 8];
                af[mi][3] = *(const uint32_t*)&Vt[o + 8 * PSTR + 8];
            }
            #pragma unroll
            for (int ni = 0; ni < 4; ni++) {
                int o = (wn * 32 + ni * 8 + g) * PSTR + kc * 16 + 2 * c;
                bf[ni][0] = *(const uint32_t*)&Pt[o];
                bf[ni][1] = *(const uint32_t*)&Pt[o + 8];
            }
            #pragma unroll
            for (int mi = 0; mi < 4; mi++)
                #pragma unroll
                for (int ni = 0; ni < 4; ni++)
                    MMA_F16(acc[mi][ni], af[mi], bf[ni]);
        }
        __syncthreads();
    }

    const float al = __ldg(alpha);
    #pragma unroll
    for (int mi = 0; mi < 4; mi++)
        #pragma unroll
        for (int ni = 0; ni < 4; ni++) {
            int cc = c0 + wm * 64 + mi * 16 + g;
            int nn = n0 + wn * 32 + ni * 8 + 2 * c;
            size_t o0 = ((size_t)b * CC + cc) * NN + nn;
            float2 xv = *(const float2*)&x[o0];
            float2 o;
            o.x = al * acc[mi][ni][0] + xv.x;
            o.y = al * acc[mi][ni][1] + xv.y;
            *(float2*)&y[o0] = o;
            size_t o1 = o0 + (size_t)8 * NN;
            xv = *(const float2*)&x[o1];
            o.x = al * acc[mi][ni][2] + xv.x;
            o.y = al * acc[mi][ni][3] + xv.y;
            *(float2*)&y[o1] = o;
        }
}

// ---------------------------------------------------------------------------
extern "C" void kernel_launch(void* const* d_in, const int* in_sizes, int n_in,
                              void* d_out, int out_size) {
    const float* x     = (const float*)d_in[0];
    const float* wq    = (const float*)d_in[1];
    const float* bq    = (const float*)d_in[2];
    const float* wk    = (const float*)d_in[3];
    const float* bk    = (const float*)d_in[4];
    const float* wv    = (const float*)d_in[5];
    const float* bv    = (const float*)d_in[6];
    const float* alpha = (const float*)d_in[7];
    float* y = (float*)d_out;

    cudaFuncSetAttribute(logits_kernel,
                         cudaFuncAttributeMaxDynamicSharedMemorySize, LOGITS_SMEM);
    cudaFuncSetAttribute(pv_kernel,
                         cudaFuncAttributeMaxDynamicSharedMemorySize, PV_SMEM);

    dim3 blk(256);

    dim3 g1(NN / 64, 640 / 64, BB);
    proj_kernel<<<g1, blk>>>(x, wq, bq, wk, bk, wv, bv);

    dim3 g2(NN / 128, NN / 128, BB);
    logits_kernel<<<g2, blk, LOGITS_SMEM>>>();

    dim3 g3(NN, BB);
    softmax_kernel<<<g3, blk>>>();

    dim3 g4(NN / 128, CC / 128, BB);
    pv_kernel<<<g4, blk, PV_SMEM>>>(x, alpha, y);
}

// round 12
// speedup vs baseline: 5.5591x; 1.4761x over previous
#include <cuda_runtime.h>
#include <cuda_bf16.h>
#include <cuda_fp16.h>
#include <cstdint>

// Problem constants
#define BB   4
#define CC   512
#define NN   4096
#define MIDD 64

// ---------------------------------------------------------------------------
// Scratch (__device__ globals; allocation-free rule).
// ---------------------------------------------------------------------------
__device__ __nv_bfloat16 g_xh[(size_t)BB * NN * CC];    // x^T hi  [b][n][c]
__device__ __nv_bfloat16 g_xl[(size_t)BB * NN * CC];    // x^T lo
__device__ __half        g_xf[(size_t)BB * NN * CC];    // x^T fp16
__device__ __nv_bfloat16 g_wqkh[128 * 512];             // [wq;wk] hi
__device__ __nv_bfloat16 g_wqkl[128 * 512];             // [wq;wk] lo
__device__ __half        g_wvf[512 * 512];              // wv fp16
__device__ __nv_bfloat16 g_qh[(size_t)BB * NN * MIDD];
__device__ __nv_bfloat16 g_ql[(size_t)BB * NN * MIDD];
__device__ __nv_bfloat16 g_kh[(size_t)BB * NN * MIDD];
__device__ __nv_bfloat16 g_kl[(size_t)BB * NN * MIDD];
__device__ __half        g_v[(size_t)BB * CC * NN];     // [b][c][n]
__device__ float         g_s[(size_t)BB * NN * NN];     // fp32 logits
__device__ __half        g_p[(size_t)BB * NN * NN];     // fp16 probs

static __device__ __forceinline__ void split2(float a, float b, uint32_t& h, uint32_t& l) {
    __nv_bfloat16 ha = __float2bfloat16_rn(a);
    __nv_bfloat16 hb = __float2bfloat16_rn(b);
    __nv_bfloat16 la = __float2bfloat16_rn(a - __bfloat162float(ha));
    __nv_bfloat16 lb = __float2bfloat16_rn(b - __bfloat162float(hb));
    __nv_bfloat162 th; th.x = ha; th.y = hb;
    __nv_bfloat162 tl; tl.x = la; tl.y = lb;
    h = *(uint32_t*)&th;  l = *(uint32_t*)&tl;
}
static __device__ __forceinline__ uint32_t packh2(float a, float b) {
    __half2 t = __floats2half2_rn(a, b);
    return *(uint32_t*)&t;
}

#define MMA_BF16(d, a, b)                                                     \
    asm volatile(                                                             \
        "mma.sync.aligned.m16n8k16.row.col.f32.bf16.bf16.f32 "                \
        "{%0,%1,%2,%3}, {%4,%5,%6,%7}, {%8,%9}, {%0,%1,%2,%3};"               \
        : "+f"(d[0]), "+f"(d[1]), "+f"(d[2]), "+f"(d[3])                      \
        : "r"(a[0]), "r"(a[1]), "r"(a[2]), "r"(a[3]), "r"(b[0]), "r"(b[1]))

#define MMA_F16(d, a, b)                                                      \
    asm volatile(                                                             \
        "mma.sync.aligned.m16n8k16.row.col.f32.f16.f16.f32 "                  \
        "{%0,%1,%2,%3}, {%4,%5,%6,%7}, {%8,%9}, {%0,%1,%2,%3};"               \
        : "+f"(d[0]), "+f"(d[1]), "+f"(d[2]), "+f"(d[3])                      \
        : "r"(a[0]), "r"(a[1]), "r"(a[2]), "r"(a[3]), "r"(b[0]), "r"(b[1]))

static __device__ __forceinline__ void cp16(uint32_t s, const void* g) {
    asm volatile("cp.async.cg.shared.global [%0], [%1], 16;\n" :: "r"(s), "l"(g) : "memory");
}
#define CP_COMMIT() asm volatile("cp.async.commit_group;\n" ::: "memory")

static __device__ __forceinline__ void ldsm4(uint32_t* r, uint32_t addr) {
    asm volatile("ldmatrix.sync.aligned.m8n8.x4.shared.b16 {%0,%1,%2,%3}, [%4];"
                 : "=r"(r[0]), "=r"(r[1]), "=r"(r[2]), "=r"(r[3]) : "r"(addr));
}

// Fragment loaders for 128-row, PSTR(40)-stride k-major tiles.
#define PSTR 40
static __device__ __forceinline__ void lda4(uint32_t a[4][4], uint32_t sb,
                                            int wm, int lane, int kc) {
    int rbase = wm * 64 + (lane & 7) + ((lane & 8) ? 8 : 0);
    int kcol = kc * 16 + ((lane & 16) ? 8 : 0);
    #pragma unroll
    for (int mi = 0; mi < 4; mi++)
        ldsm4(a[mi], sb + (uint32_t)(((rbase + mi * 16) * PSTR + kcol) * 2));
}
static __device__ __forceinline__ void ldb4(uint32_t bf[4][2], uint32_t sb,
                                            int wn, int lane, int kc) {
    int rb = wn * 32 + (lane & 7) + ((lane & 16) ? 8 : 0);
    int kcol = kc * 16 + ((lane & 8) ? 8 : 0);
    #pragma unroll
    for (int nip = 0; nip < 4; nip += 2) {
        uint32_t r[4];
        ldsm4(r, sb + (uint32_t)(((rb + nip * 8) * PSTR + kcol) * 2));
        bf[nip][0] = r[0]; bf[nip][1] = r[1];
        bf[nip + 1][0] = r[2]; bf[nip + 1][1] = r[3];
    }
}

// ---------------------------------------------------------------------------
// Kernel A: transpose+convert x[b][c][n] -> xh/xl (bf16 split), xf (fp16), [b][n][c]
// ---------------------------------------------------------------------------
__global__ __launch_bounds__(256)
void xconv_kernel(const float* __restrict__ x) {
    __shared__ float t[64][65];
    const int n0 = blockIdx.x * 64, c0 = blockIdx.y * 64, b = blockIdx.z;
    const int tid = threadIdx.x;
    const float* xb = x + ((size_t)b * CC + c0) * NN + n0;
    #pragma unroll
    for (int i = tid; i < 1024; i += 256) {
        int r = i >> 4, q = i & 15;
        float4 v = *(const float4*)&xb[(size_t)r * NN + q * 4];
        t[r][q * 4 + 0] = v.x; t[r][q * 4 + 1] = v.y;
        t[r][q * 4 + 2] = v.z; t[r][q * 4 + 3] = v.w;
    }
    __syncthreads();
    #pragma unroll
    for (int i = tid; i < 1024; i += 256) {
        int n = i >> 4, qd = i & 15;
        float v0 = t[qd * 4 + 0][n], v1 = t[qd * 4 + 1][n];
        float v2 = t[qd * 4 + 2][n], v3 = t[qd * 4 + 3][n];
        uint2 uh, ul, uf;
        split2(v0, v1, uh.x, ul.x);
        split2(v2, v3, uh.y, ul.y);
        uf.x = packh2(v0, v1); uf.y = packh2(v2, v3);
        size_t off = ((size_t)b * NN + n0 + n) * CC + c0 + qd * 4;
        *(uint2*)&g_xh[off] = uh;
        *(uint2*)&g_xl[off] = ul;
        *(uint2*)&g_xf[off] = uf;
    }
}

// ---------------------------------------------------------------------------
// Kernel B: weight conversion. [wq;wk] -> split bf16; wv -> fp16.
// ---------------------------------------------------------------------------
__global__ __launch_bounds__(256)
void wconv_kernel(const float* __restrict__ wq, const float* __restrict__ wk,
                  const float* __restrict__ wv) {
    int idx = blockIdx.x * 256 + threadIdx.x;
    if (idx < 128 * 512) {
        int m = idx >> 9, k = idx & 511;
        float v = (m < 64) ? wq[m * 512 + k] : wk[(m - 64) * 512 + k];
        __nv_bfloat16 h = __float2bfloat16_rn(v);
        g_wqkh[idx] = h;
        g_wqkl[idx] = __float2bfloat16_rn(v - __bfloat162float(h));
    } else {
        int j = idx - 65536;
        if (j < 262144) g_wvf[j] = __float2half_rn(wv[j]);
    }
}

// ---------------------------------------------------------------------------
// Kernel C: q/k projection via 3-pass split-bf16 HMMA.
// D[n][m] = sum_k x^T[n][k] * Wqk[m][k]; m 0-63 -> q, 64-127 -> k. k = 512.
// Tile 128n x 128m, k-tile 32, 3-stage cp.async pipeline.
// ---------------------------------------------------------------------------
#define TSTR_H (128 * PSTR)               // 5120 halves per 128x32 stream
#define QK_STG_H (4 * TSTR_H)             // xh | xl | wh | wl
#define QK_SMEM (3 * QK_STG_H * 2)

__global__ __launch_bounds__(256)
void proj_qk_kernel(const float* __restrict__ bq, const float* __restrict__ bk) {
    const int n0 = blockIdx.x * 128, b = blockIdx.z;
    extern __shared__ __align__(16) __nv_bfloat16 qsm[];
    const uint32_t sbase = (uint32_t)__cvta_generic_to_shared(qsm);

    const int tid = threadIdx.x;
    const int wid = tid >> 5, lane = tid & 31;
    const int wm = wid >> 2, wn = wid & 3;
    const int g = lane >> 2, c = lane & 3;

    const __nv_bfloat16* xh = g_xh + ((size_t)b * NN + n0) * CC;
    const __nv_bfloat16* xl = g_xl + ((size_t)b * NN + n0) * CC;

    const int lr = tid >> 1, lc0 = (tid & 1) * 2;

    auto load_tile = [&](int stage, int k0) {
        uint32_t st = sbase + (uint32_t)(stage * QK_STG_H * 2);
        #pragma unroll
        for (int q = 0; q < 2; q++) {
            int c8 = lc0 + q;
            uint32_t so = lr * (PSTR * 2) + c8 * 16;
            cp16(st + so,                 &xh[(size_t)lr * CC + k0 + c8 * 8]);
            cp16(st + TSTR_H * 2 + so,    &xl[(size_t)lr * CC + k0 + c8 * 8]);
            cp16(st + TSTR_H * 4 + so,    &g_wqkh[lr * 512 + k0 + c8 * 8]);
            cp16(st + TSTR_H * 6 + so,    &g_wqkl[lr * 512 + k0 + c8 * 8]);
        }
        CP_COMMIT();
    };

    load_tile(0, 0);
    load_tile(1, 32);

    float acc[4][4][4] = {};
    const int NT = 512 / 32;   // 16

    for (int jt = 0; jt < NT; jt++) {
        if (jt == NT - 1) asm volatile("cp.async.wait_group 0;\n" ::: "memory");
        else              asm volatile("cp.async.wait_group 1;\n" ::: "memory");
        __syncthreads();
        if (jt + 2 < NT) load_tile((jt + 2) % 3, (jt + 2) * 32);

        uint32_t st = sbase + (uint32_t)((jt % 3) * QK_STG_H * 2);
        #pragma unroll
        for (int kc = 0; kc < 2; kc++) {
            uint32_t afh[4][4], afl[4][4], bfh[4][2], bfl[4][2];
            lda4(afh, st,               wm, lane, kc);
            lda4(afl, st + TSTR_H * 2,  wm, lane, kc);
            ldb4(bfh, st + TSTR_H * 4,  wn, lane, kc);
            ldb4(bfl, st + TSTR_H * 6,  wn, lane, kc);
            #pragma unroll
            for (int mi = 0; mi < 4; mi++)
                #pragma unroll
                for (int ni = 0; ni < 4; ni++) {
                    MMA_BF16(acc[mi][ni], afh[mi], bfh[ni]);
                    MMA_BF16(acc[mi][ni], afh[mi], bfl[ni]);
                    MMA_BF16(acc[mi][ni], afl[mi], bfh[ni]);
                }
        }
    }

    #pragma unroll
    for (int ni = 0; ni < 4; ni++) {
        int col = wn * 32 + ni * 8 + 2 * c;
        bool isq = (col < 64);
        const float* bb = isq ? bq : bk;
        int cm = col & 63;
        float b0 = bb[cm], b1 = bb[cm + 1];
        __nv_bfloat16* dh = isq ? g_qh : g_kh;
        __nv_bfloat16* dl = isq ? g_ql : g_kl;
        #pragma unroll
        for (int mi = 0; mi < 4; mi++) {
            int r = n0 + wm * 64 + mi * 16 + g;
            uint32_t uh, ul;
            split2(acc[mi][ni][0] + b0, acc[mi][ni][1] + b1, uh, ul);
            size_t o0 = ((size_t)b * NN + r) * MIDD + cm;
            *(uint32_t*)&dh[o0] = uh;
            *(uint32_t*)&dl[o0] = ul;
            split2(acc[mi][ni][2] + b0, acc[mi][ni][3] + b1, uh, ul);
            size_t o1 = ((size_t)b * NN + r + 8) * MIDD + cm;
            *(uint32_t*)&dh[o1] = uh;
            *(uint32_t*)&dl[o1] = ul;
        }
    }
}

// ---------------------------------------------------------------------------
// Kernel D: V projection via single-pass fp16 HMMA.
// V[c][n] = sum_k wv[c][k] * x^T[n][k] + bv[c]. Tile 128c x 128n, k = 512.
// ---------------------------------------------------------------------------
#define V_STG_H (2 * TSTR_H)
#define V_SMEM (3 * V_STG_H * 2)

__global__ __launch_bounds__(256)
void proj_v_kernel(const float* __restrict__ bv) {
    const int n0 = blockIdx.x * 128, c0 = blockIdx.y * 128, b = blockIdx.z;
    extern __shared__ __align__(16) __half vsm[];
    const uint32_t sbase = (uint32_t)__cvta_generic_to_shared(vsm);

    const int tid = threadIdx.x;
    const int wid = tid >> 5, lane = tid & 31;
    const int wm = wid >> 2, wn = wid & 3;
    const int g = lane >> 2, c = lane & 3;

    const __half* wv = g_wvf + (size_t)c0 * 512;
    const __half* xf = g_xf + ((size_t)b * NN + n0) * CC;

    const int lr = tid >> 1, lc0 = (tid & 1) * 2;

    auto load_tile = [&](int stage, int k0) {
        uint32_t st = sbase + (uint32_t)(stage * V_STG_H * 2);
        #pragma unroll
        for (int q = 0; q < 2; q++) {
            int c8 = lc0 + q;
            uint32_t so = lr * (PSTR * 2) + c8 * 16;
            cp16(st + so,              &wv[(size_t)lr * 512 + k0 + c8 * 8]);
            cp16(st + TSTR_H * 2 + so, &xf[(size_t)lr * CC + k0 + c8 * 8]);
        }
        CP_COMMIT();
    };

    load_tile(0, 0);
    load_tile(1, 32);

    float acc[4][4][4] = {};
    const int NT = 512 / 32;

    for (int jt = 0; jt < NT; jt++) {
        if (jt == NT - 1) asm volatile("cp.async.wait_group 0;\n" ::: "memory");
        else              asm volatile("cp.async.wait_group 1;\n" ::: "memory");
        __syncthreads();
        if (jt + 2 < NT) load_tile((jt + 2) % 3, (jt + 2) * 32);

        uint32_t st = sbase + (uint32_t)((jt % 3) * V_STG_H * 2);
        #pragma unroll
        for (int kc = 0; kc < 2; kc++) {
            uint32_t af[4][4], bf[4][2];
            lda4(af, st,              wm, lane, kc);
            ldb4(bf, st + TSTR_H * 2, wn, lane, kc);
            #pragma unroll
            for (int mi = 0; mi < 4; mi++)
                #pragma unroll
                for (int ni = 0; ni < 4; ni++)
                    MMA_F16(acc[mi][ni], af[mi], bf[ni]);
        }
    }

    #pragma unroll
    for (int mi = 0; mi < 4; mi++) {
        int cc = c0 + wm * 64 + mi * 16 + g;
        float b0 = bv[cc], b2 = bv[cc + 8];
        #pragma unroll
        for (int ni = 0; ni < 4; ni++) {
            int nn = n0 + wn * 32 + ni * 8 + 2 * c;
            size_t o0 = ((size_t)b * CC + cc) * NN + nn;
            *(uint32_t*)&g_v[o0] = packh2(acc[mi][ni][0] + b0, acc[mi][ni][1] + b0);
            size_t o1 = o0 + (size_t)8 * NN;
            *(uint32_t*)&g_v[o1] = packh2(acc[mi][ni][2] + b2, acc[mi][ni][3] + b2);
        }
    }
}

// ---------------------------------------------------------------------------
// Kernel 2: logits via split-bf16 HMMA (3 passes). S[i][j]=sum_m Q[i][m]K[j][m].
// ---------------------------------------------------------------------------
#define LSTR 72
#define LOGITS_SMEM (4 * 128 * LSTR * 2)

__global__ __launch_bounds__(256)
void logits_kernel() {
    const int j0 = blockIdx.x * 128;
    const int i0 = blockIdx.y * 128;
    const int b  = blockIdx.z;

    extern __shared__ __align__(16) __nv_bfloat16 lsm[];
    __nv_bfloat16* sQh = lsm;
    __nv_bfloat16* sQl = lsm + 128 * LSTR;
    __nv_bfloat16* sKh = lsm + 2 * 128 * LSTR;
    __nv_bfloat16* sKl = lsm + 3 * 128 * LSTR;

    const int tid = threadIdx.x;
    const int wid = tid >> 5, lane = tid & 31;
    const int wm = wid >> 2, wn = wid & 3;
    const int g = lane >> 2, c = lane & 3;

    const size_t qoff = (size_t)b * NN * MIDD;

    #pragma unroll
    for (int i = tid; i < 1024; i += 256) {
        int r = i >> 3, c8 = i & 7;
        size_t go = qoff + (size_t)(i0 + r) * MIDD + c8 * 8;
        size_t ko = qoff + (size_t)(j0 + r) * MIDD + c8 * 8;
        int so = r * LSTR + c8 * 8;
        *(uint4*)&sQh[so] = *(const uint4*)&g_qh[go];
        *(uint4*)&sQl[so] = *(const uint4*)&g_ql[go];
        *(uint4*)&sKh[so] = *(const uint4*)&g_kh[ko];
        *(uint4*)&sKl[so] = *(const uint4*)&g_kl[ko];
    }
    __syncthreads();

    float acc[4][4][4] = {};

    #pragma unroll
    for (int kc = 0; kc < 4; kc++) {
        uint32_t afh[4][4], afl[4][4], bfh[4][2], bfl[4][2];
        #pragma unroll
        for (int mi = 0; mi < 4; mi++) {
            int o = (wm * 64 + mi * 16 + g) * LSTR + kc * 16 + 2 * c;
            afh[mi][0] = *(const uint32_t*)&sQh[o];
            afh[mi][1] = *(const uint32_t*)&sQh[o + 8 * LSTR];
            afh[mi][2] = *(const uint32_t*)&sQh[o + 8];
            afh[mi][3] = *(const uint32_t*)&sQh[o + 8 * LSTR + 8];
            afl[mi][0] = *(const uint32_t*)&sQl[o];
            afl[mi][1] = *(const uint32_t*)&sQl[o + 8 * LSTR];
            afl[mi][2] = *(const uint32_t*)&sQl[o + 8];
            afl[mi][3] = *(const uint32_t*)&sQl[o + 8 * LSTR + 8];
        }
        #pragma unroll
        for (int ni = 0; ni < 4; ni++) {
            int o = (wn * 32 + ni * 8 + g) * LSTR + kc * 16 + 2 * c;
            bfh[ni][0] = *(const uint32_t*)&sKh[o];
            bfh[ni][1] = *(const uint32_t*)&sKh[o + 8];
            bfl[ni][0] = *(const uint32_t*)&sKl[o];
            bfl[ni][1] = *(const uint32_t*)&sKl[o + 8];
        }
        #pragma unroll
        for (int mi = 0; mi < 4; mi++)
            #pragma unroll
            for (int ni = 0; ni < 4; ni++) {
                MMA_BF16(acc[mi][ni], afh[mi], bfh[ni]);
                MMA_BF16(acc[mi][ni], afh[mi], bfl[ni]);
                MMA_BF16(acc[mi][ni], afl[mi], bfh[ni]);
            }
    }

    float* sb = g_s + ((size_t)b * NN + i0) * NN + j0;
    #pragma unroll
    for (int mi = 0; mi < 4; mi++)
        #pragma unroll
        for (int ni = 0; ni < 4; ni++) {
            int r = wm * 64 + mi * 16 + g;
            int cn = wn * 32 + ni * 8 + 2 * c;
            float2 v0 = {acc[mi][ni][0], acc[mi][ni][1]};
            float2 v1 = {acc[mi][ni][2], acc[mi][ni][3]};
            *(float2*)&sb[(size_t)r * NN + cn] = v0;
            *(float2*)&sb[(size_t)(r + 8) * NN + cn] = v1;
        }
}

// ---------------------------------------------------------------------------
// Kernel 3: row softmax. Reads fp32 logits, writes fp16 probs.
// ---------------------------------------------------------------------------
__global__ __launch_bounds__(256, 8)
void softmax_kernel() {
    const int row = blockIdx.x;
    const int b   = blockIdx.y;
    const float* s = g_s + ((size_t)b * NN + row) * NN;
    __half* p = g_p + ((size_t)b * NN + row) * NN;

    const int tid = threadIdx.x;
    float4 v[4];
    #pragma unroll
    for (int i = 0; i < 4; i++)
        v[i] = *(const float4*)&s[tid * 16 + i * 4];

    float m = v[0].x;
    #pragma unroll
    for (int i = 0; i < 4; i++) {
        m = fmaxf(m, v[i].x); m = fmaxf(m, v[i].y);
        m = fmaxf(m, v[i].z); m = fmaxf(m, v[i].w);
    }
    __shared__ float red[8];
    #pragma unroll
    for (int off = 16; off > 0; off >>= 1)
        m = fmaxf(m, __shfl_xor_sync(0xffffffffu, m, off));
    if ((tid & 31) == 0) red[tid >> 5] = m;
    __syncthreads();
    m = red[0];
    #pragma unroll
    for (int w = 1; w < 8; w++) m = fmaxf(m, red[w]);
    __syncthreads();

    float sum = 0.f;
    #pragma unroll
    for (int i = 0; i < 4; i++) {
        v[i].x = __expf(v[i].x - m); sum += v[i].x;
        v[i].y = __expf(v[i].y - m); sum += v[i].y;
        v[i].z = __expf(v[i].z - m); sum += v[i].z;
        v[i].w = __expf(v[i].w - m); sum += v[i].w;
    }
    #pragma unroll
    for (int off = 16; off > 0; off >>= 1)
        sum += __shfl_xor_sync(0xffffffffu, sum, off);
    if ((tid & 31) == 0) red[tid >> 5] = sum;
    __syncthreads();
    sum = 0.f;
    #pragma unroll
    for (int w = 0; w < 8; w++) sum += red[w];
    const float inv = 1.0f / sum;

    uint32_t hh[8];
    #pragma unroll
    for (int i = 0; i < 4; i++) {
        hh[2 * i]     = packh2(v[i].x * inv, v[i].y * inv);
        hh[2 * i + 1] = packh2(v[i].z * inv, v[i].w * inv);
    }
    uint4 u;
    u = make_uint4(hh[0], hh[1], hh[2], hh[3]); *(uint4*)&p[tid * 16] = u;
    u = make_uint4(hh[4], hh[5], hh[6], hh[7]); *(uint4*)&p[tid * 16 + 8] = u;
}

// ---------------------------------------------------------------------------
// Kernel 4: PV via fp16 HMMA, ldmatrix fragments, 3-stage cp.async pipeline.
// Out^T[c][n] = sum_j V[c][j] * P[n][j];  y[b][c][n] = alpha*Out + x.
// ---------------------------------------------------------------------------
#define PV_STG_H (2 * TSTR_H)
#define PV_SMEM (3 * PV_STG_H * 2)

__global__ __launch_bounds__(256)
void pv_kernel(const float* __restrict__ x,
               const float* __restrict__ alpha,
               float* __restrict__ y) {
    const int n0 = blockIdx.x * 128;
    const int c0 = blockIdx.y * 128;
    const int b  = blockIdx.z;

    extern __shared__ __align__(16) __half psm[];
    const uint32_t sbase = (uint32_t)__cvta_generic_to_shared(psm);

    const int tid = threadIdx.x;
    const int wid = tid >> 5, lane = tid & 31;
    const int wm = wid >> 2, wn = wid & 3;
    const int g = lane >> 2, c = lane & 3;

    const __half* vv = g_v + (size_t)(b * CC + c0) * NN;
    const __half* pp = g_p + ((size_t)b * NN + n0) * NN;

    const int lr = tid >> 1, lc0 = (tid & 1) * 2;

    auto load_tile = [&](int stage, int j0) {
        uint32_t st = sbase + (uint32_t)(stage * PV_STG_H * 2);
        #pragma unroll
        for (int q = 0; q < 2; q++) {
            int c8 = lc0 + q;
            uint32_t so = lr * (PSTR * 2) + c8 * 16;
            cp16(st + so,              &vv[(size_t)lr * NN + j0 + c8 * 8]);
            cp16(st + TSTR_H * 2 + so, &pp[(size_t)lr * NN + j0 + c8 * 8]);
        }
        CP_COMMIT();
    };

    load_tile(0, 0);
    load_tile(1, 32);

    float acc[4][4][4] = {};
    const int NT = NN / 32;   // 128

    for (int jt = 0; jt < NT; jt++) {
        if (jt == NT - 1) asm volatile("cp.async.wait_group 0;\n" ::: "memory");
        else              asm volatile("cp.async.wait_group 1;\n" ::: "memory");
        __syncthreads();
        if (jt + 2 < NT) load_tile((jt + 2) % 3, (jt + 2) * 32);

        uint32_t st = sbase + (uint32_t)((jt % 3) * PV_STG_H * 2);
        #pragma unroll
        for (int kc = 0; kc < 2; kc++) {
            uint32_t af[4][4], bf[4][2];
            lda4(af, st,              wm, lane, kc);
            ldb4(bf, st + TSTR_H * 2, wn, lane, kc);
            #pragma unroll
            for (int mi = 0; mi < 4; mi++)
                #pragma unroll
                for (int ni = 0; ni < 4; ni++)
                    MMA_F16(acc[mi][ni], af[mi], bf[ni]);
        }
    }

    const float al = __ldg(alpha);
    #pragma unroll
    for (int mi = 0; mi < 4; mi++)
        #pragma unroll
        for (int ni = 0; ni < 4; ni++) {
            int cc = c0 + wm * 64 + mi * 16 + g;
            int nn = n0 + wn * 32 + ni * 8 + 2 * c;
            size_t o0 = ((size_t)b * CC + cc) * NN + nn;
            float2 xv = *(const float2*)&x[o0];
            float2 o;
            o.x = al * acc[mi][ni][0] + xv.x;
            o.y = al * acc[mi][ni][1] + xv.y;
            *(float2*)&y[o0] = o;
            size_t o1 = o0 + (size_t)8 * NN;
            xv = *(const float2*)&x[o1];
            o.x = al * acc[mi][ni][2] + xv.x;
            o.y = al * acc[mi][ni][3] + xv.y;
            *(float2*)&y[o1] = o;
        }
}

// ---------------------------------------------------------------------------
extern "C" void kernel_launch(void* const* d_in, const int* in_sizes, int n_in,
                              void* d_out, int out_size) {
    const float* x     = (const float*)d_in[0];
    const float* wq    = (const float*)d_in[1];
    const float* bq    = (const float*)d_in[2];
    const float* wk    = (const float*)d_in[3];
    const float* bk    = (const float*)d_in[4];
    const float* wv    = (const float*)d_in[5];
    const float* bv    = (const float*)d_in[6];
    const float* alpha = (const float*)d_in[7];
    float* y = (float*)d_out;

    cudaFuncSetAttribute(proj_qk_kernel,
                         cudaFuncAttributeMaxDynamicSharedMemorySize, QK_SMEM);
    cudaFuncSetAttribute(proj_v_kernel,
                         cudaFuncAttributeMaxDynamicSharedMemorySize, V_SMEM);
    cudaFuncSetAttribute(logits_kernel,
                         cudaFuncAttributeMaxDynamicSharedMemorySize, LOGITS_SMEM);
    cudaFuncSetAttribute(pv_kernel,
                         cudaFuncAttributeMaxDynamicSharedMemorySize, PV_SMEM);

    dim3 blk(256);

    xconv_kernel<<<dim3(NN / 64, CC / 64, BB), blk>>>(x);
    wconv_kernel<<<1280, blk>>>(wq, wk, wv);
    proj_qk_kernel<<<dim3(NN / 128, 1, BB), blk, QK_SMEM>>>(bq, bk);
    proj_v_kernel<<<dim3(NN / 128, CC / 128, BB), blk, V_SMEM>>>(bv);
    logits_kernel<<<dim3(NN / 128, NN / 128, BB), blk, LOGITS_SMEM>>>();
    softmax_kernel<<<dim3(NN, BB), blk>>>();
    pv_kernel<<<dim3(NN / 128, CC / 128, BB), blk, PV_SMEM>>>(x, alpha, y);
}

// round 13
// speedup vs baseline: 5.8511x; 1.0525x over previous
#include <cuda_runtime.h>
#include <cuda_bf16.h>
#include <cuda_fp16.h>
#include <cstdint>

// Problem constants
#define BB   4
#define CC   512
#define NN   4096
#define MIDD 64

// ---------------------------------------------------------------------------
// Scratch (__device__ globals; allocation-free rule).
// ---------------------------------------------------------------------------
__device__ __nv_bfloat16 g_xh[(size_t)BB * NN * CC];    // x^T hi  [b][n][c]
__device__ __nv_bfloat16 g_xl[(size_t)BB * NN * CC];    // x^T lo
__device__ __half        g_xf[(size_t)BB * NN * CC];    // x^T fp16
__device__ __nv_bfloat16 g_wqkh[128 * 512];             // [wq;wk] hi
__device__ __nv_bfloat16 g_wqkl[128 * 512];             // [wq;wk] lo
__device__ __half        g_wvf[512 * 512];              // wv fp16
__device__ __nv_bfloat16 g_qh[(size_t)BB * NN * MIDD];
__device__ __nv_bfloat16 g_ql[(size_t)BB * NN * MIDD];
__device__ __nv_bfloat16 g_kh[(size_t)BB * NN * MIDD];
__device__ __nv_bfloat16 g_kl[(size_t)BB * NN * MIDD];
__device__ __half        g_v[(size_t)BB * CC * NN];     // [b][c][n]
__device__ float         g_s[(size_t)BB * NN * NN];     // fp32 logits
__device__ __half        g_p[(size_t)BB * NN * NN];     // fp16 probs

static __device__ __forceinline__ void split2(float a, float b, uint32_t& h, uint32_t& l) {
    __nv_bfloat16 ha = __float2bfloat16_rn(a);
    __nv_bfloat16 hb = __float2bfloat16_rn(b);
    __nv_bfloat16 la = __float2bfloat16_rn(a - __bfloat162float(ha));
    __nv_bfloat16 lb = __float2bfloat16_rn(b - __bfloat162float(hb));
    __nv_bfloat162 th; th.x = ha; th.y = hb;
    __nv_bfloat162 tl; tl.x = la; tl.y = lb;
    h = *(uint32_t*)&th;  l = *(uint32_t*)&tl;
}
static __device__ __forceinline__ uint32_t packh2(float a, float b) {
    __half2 t = __floats2half2_rn(a, b);
    return *(uint32_t*)&t;
}

#define MMA_BF16(d, a, b)                                                     \
    asm volatile(                                                             \
        "mma.sync.aligned.m16n8k16.row.col.f32.bf16.bf16.f32 "                \
        "{%0,%1,%2,%3}, {%4,%5,%6,%7}, {%8,%9}, {%0,%1,%2,%3};"               \
        : "+f"(d[0]), "+f"(d[1]), "+f"(d[2]), "+f"(d[3])                      \
        : "r"(a[0]), "r"(a[1]), "r"(a[2]), "r"(a[3]), "r"(b[0]), "r"(b[1]))

#define MMA_F16(d, a, b)                                                      \
    asm volatile(                                                             \
        "mma.sync.aligned.m16n8k16.row.col.f32.f16.f16.f32 "                  \
        "{%0,%1,%2,%3}, {%4,%5,%6,%7}, {%8,%9}, {%0,%1,%2,%3};"               \
        : "+f"(d[0]), "+f"(d[1]), "+f"(d[2]), "+f"(d[3])                      \
        : "r"(a[0]), "r"(a[1]), "r"(a[2]), "r"(a[3]), "r"(b[0]), "r"(b[1]))

static __device__ __forceinline__ void cp16(uint32_t s, const void* g) {
    asm volatile("cp.async.cg.shared.global [%0], [%1], 16;\n" :: "r"(s), "l"(g) : "memory");
}
#define CP_COMMIT() asm volatile("cp.async.commit_group;\n" ::: "memory")

static __device__ __forceinline__ void ldsm4(uint32_t* r, uint32_t addr) {
    asm volatile("ldmatrix.sync.aligned.m8n8.x4.shared.b16 {%0,%1,%2,%3}, [%4];"
                 : "=r"(r[0]), "=r"(r[1]), "=r"(r[2]), "=r"(r[3]) : "r"(addr));
}

// Fragment loaders for PSTR(40)-stride k-major tiles.
#define PSTR 40
static __device__ __forceinline__ void lda4(uint32_t a[4][4], uint32_t sb,
                                            int wm, int lane, int kc) {
    int rbase = wm * 64 + (lane & 7) + ((lane & 8) ? 8 : 0);
    int kcol = kc * 16 + ((lane & 16) ? 8 : 0);
    #pragma unroll
    for (int mi = 0; mi < 4; mi++)
        ldsm4(a[mi], sb + (uint32_t)(((rbase + mi * 16) * PSTR + kcol) * 2));
}
static __device__ __forceinline__ void ldb4(uint32_t bf[][2], uint32_t sb,
                                            int wn, int lane, int kc) {
    int rb = wn * 32 + (lane & 7) + ((lane & 16) ? 8 : 0);
    int kcol = kc * 16 + ((lane & 8) ? 8 : 0);
    #pragma unroll
    for (int nip = 0; nip < 4; nip += 2) {
        uint32_t r[4];
        ldsm4(r, sb + (uint32_t)(((rb + nip * 8) * PSTR + kcol) * 2));
        bf[nip][0] = r[0]; bf[nip][1] = r[1];
        bf[nip + 1][0] = r[2]; bf[nip + 1][1] = r[3];
    }
}

// ---------------------------------------------------------------------------
// Kernel A: transpose+convert x[b][c][n] -> xh/xl (bf16 split), xf (fp16), [b][n][c]
// ---------------------------------------------------------------------------
__global__ __launch_bounds__(256)
void xconv_kernel(const float* __restrict__ x) {
    __shared__ float t[64][65];
    const int n0 = blockIdx.x * 64, c0 = blockIdx.y * 64, b = blockIdx.z;
    const int tid = threadIdx.x;
    const float* xb = x + ((size_t)b * CC + c0) * NN + n0;
    #pragma unroll
    for (int i = tid; i < 1024; i += 256) {
        int r = i >> 4, q = i & 15;
        float4 v = *(const float4*)&xb[(size_t)r * NN + q * 4];
        t[r][q * 4 + 0] = v.x; t[r][q * 4 + 1] = v.y;
        t[r][q * 4 + 2] = v.z; t[r][q * 4 + 3] = v.w;
    }
    __syncthreads();
    #pragma unroll
    for (int i = tid; i < 1024; i += 256) {
        int n = i >> 4, qd = i & 15;
        float v0 = t[qd * 4 + 0][n], v1 = t[qd * 4 + 1][n];
        float v2 = t[qd * 4 + 2][n], v3 = t[qd * 4 + 3][n];
        uint2 uh, ul, uf;
        split2(v0, v1, uh.x, ul.x);
        split2(v2, v3, uh.y, ul.y);
        uf.x = packh2(v0, v1); uf.y = packh2(v2, v3);
        size_t off = ((size_t)b * NN + n0 + n) * CC + c0 + qd * 4;
        *(uint2*)&g_xh[off] = uh;
        *(uint2*)&g_xl[off] = ul;
        *(uint2*)&g_xf[off] = uf;
    }
}

// ---------------------------------------------------------------------------
// Kernel B: weight conversion. [wq;wk] -> split bf16; wv -> fp16.
// ---------------------------------------------------------------------------
__global__ __launch_bounds__(256)
void wconv_kernel(const float* __restrict__ wq, const float* __restrict__ wk,
                  const float* __restrict__ wv) {
    int idx = blockIdx.x * 256 + threadIdx.x;
    if (idx < 128 * 512) {
        int m = idx >> 9, k = idx & 511;
        float v = (m < 64) ? wq[m * 512 + k] : wk[(m - 64) * 512 + k];
        __nv_bfloat16 h = __float2bfloat16_rn(v);
        g_wqkh[idx] = h;
        g_wqkl[idx] = __float2bfloat16_rn(v - __bfloat162float(h));
    } else {
        int j = idx - 65536;
        if (j < 262144) g_wvf[j] = __float2half_rn(wv[j]);
    }
}

// ---------------------------------------------------------------------------
// Kernel C: q/k projection via 3-pass split-bf16 HMMA.
// D[n][m] = sum_k x^T[n][k] * Wqk[m][k]; m 0-63 -> q, 64-127 -> k. k = 512.
// ---------------------------------------------------------------------------
#define TSTR_H (128 * PSTR)               // 5120 halves per 128x32 stream
#define QK_STG_H (4 * TSTR_H)             // xh | xl | wh | wl
#define QK_SMEM (3 * QK_STG_H * 2)

__global__ __launch_bounds__(256)
void proj_qk_kernel(const float* __restrict__ bq, const float* __restrict__ bk) {
    const int n0 = blockIdx.x * 128, b = blockIdx.z;
    extern __shared__ __align__(16) __nv_bfloat16 qsm[];
    const uint32_t sbase = (uint32_t)__cvta_generic_to_shared(qsm);

    const int tid = threadIdx.x;
    const int wid = tid >> 5, lane = tid & 31;
    const int wm = wid >> 2, wn = wid & 3;
    const int g = lane >> 2, c = lane & 3;

    const __nv_bfloat16* xh = g_xh + ((size_t)b * NN + n0) * CC;
    const __nv_bfloat16* xl = g_xl + ((size_t)b * NN + n0) * CC;

    const int lr = tid >> 1, lc0 = (tid & 1) * 2;

    auto load_tile = [&](int stage, int k0) {
        uint32_t st = sbase + (uint32_t)(stage * QK_STG_H * 2);
        #pragma unroll
        for (int q = 0; q < 2; q++) {
            int c8 = lc0 + q;
            uint32_t so = lr * (PSTR * 2) + c8 * 16;
            cp16(st + so,                 &xh[(size_t)lr * CC + k0 + c8 * 8]);
            cp16(st + TSTR_H * 2 + so,    &xl[(size_t)lr * CC + k0 + c8 * 8]);
            cp16(st + TSTR_H * 4 + so,    &g_wqkh[lr * 512 + k0 + c8 * 8]);
            cp16(st + TSTR_H * 6 + so,    &g_wqkl[lr * 512 + k0 + c8 * 8]);
        }
        CP_COMMIT();
    };

    load_tile(0, 0);
    load_tile(1, 32);

    float acc[4][4][4] = {};
    const int NT = 512 / 32;   // 16

    for (int jt = 0; jt < NT; jt++) {
        if (jt == NT - 1) asm volatile("cp.async.wait_group 0;\n" ::: "memory");
        else              asm volatile("cp.async.wait_group 1;\n" ::: "memory");
        __syncthreads();
        if (jt + 2 < NT) load_tile((jt + 2) % 3, (jt + 2) * 32);

        uint32_t st = sbase + (uint32_t)((jt % 3) * QK_STG_H * 2);
        #pragma unroll
        for (int kc = 0; kc < 2; kc++) {
            uint32_t afh[4][4], afl[4][4], bfh[4][2], bfl[4][2];
            lda4(afh, st,               wm, lane, kc);
            lda4(afl, st + TSTR_H * 2,  wm, lane, kc);
            ldb4(bfh, st + TSTR_H * 4,  wn, lane, kc);
            ldb4(bfl, st + TSTR_H * 6,  wn, lane, kc);
            #pragma unroll
            for (int mi = 0; mi < 4; mi++)
                #pragma unroll
                for (int ni = 0; ni < 4; ni++) {
                    MMA_BF16(acc[mi][ni], afh[mi], bfh[ni]);
                    MMA_BF16(acc[mi][ni], afh[mi], bfl[ni]);
                    MMA_BF16(acc[mi][ni], afl[mi], bfh[ni]);
                }
        }
    }

    #pragma unroll
    for (int ni = 0; ni < 4; ni++) {
        int col = wn * 32 + ni * 8 + 2 * c;
        bool isq = (col < 64);
        const float* bb = isq ? bq : bk;
        int cm = col & 63;
        float b0 = bb[cm], b1 = bb[cm + 1];
        __nv_bfloat16* dh = isq ? g_qh : g_kh;
        __nv_bfloat16* dl = isq ? g_ql : g_kl;
        #pragma unroll
        for (int mi = 0; mi < 4; mi++) {
            int r = n0 + wm * 64 + mi * 16 + g;
            uint32_t uh, ul;
            split2(acc[mi][ni][0] + b0, acc[mi][ni][1] + b1, uh, ul);
            size_t o0 = ((size_t)b * NN + r) * MIDD + cm;
            *(uint32_t*)&dh[o0] = uh;
            *(uint32_t*)&dl[o0] = ul;
            split2(acc[mi][ni][2] + b0, acc[mi][ni][3] + b1, uh, ul);
            size_t o1 = ((size_t)b * NN + r + 8) * MIDD + cm;
            *(uint32_t*)&dh[o1] = uh;
            *(uint32_t*)&dl[o1] = ul;
        }
    }
}

// ---------------------------------------------------------------------------
// Kernel D: V projection via single-pass fp16 HMMA.
// V[c][n] = sum_k wv[c][k] * x^T[n][k] + bv[c]. Tile 128c x 128n, k = 512.
// ---------------------------------------------------------------------------
#define V_STG_H (2 * TSTR_H)
#define V_SMEM (3 * V_STG_H * 2)

__global__ __launch_bounds__(256)
void proj_v_kernel(const float* __restrict__ bv) {
    const int n0 = blockIdx.x * 128, c0 = blockIdx.y * 128, b = blockIdx.z;
    extern __shared__ __align__(16) __half vsm[];
    const uint32_t sbase = (uint32_t)__cvta_generic_to_shared(vsm);

    const int tid = threadIdx.x;
    const int wid = tid >> 5, lane = tid & 31;
    const int wm = wid >> 2, wn = wid & 3;
    const int g = lane >> 2, c = lane & 3;

    const __half* wv = g_wvf + (size_t)c0 * 512;
    const __half* xf = g_xf + ((size_t)b * NN + n0) * CC;

    const int lr = tid >> 1, lc0 = (tid & 1) * 2;

    auto load_tile = [&](int stage, int k0) {
        uint32_t st = sbase + (uint32_t)(stage * V_STG_H * 2);
        #pragma unroll
        for (int q = 0; q < 2; q++) {
            int c8 = lc0 + q;
            uint32_t so = lr * (PSTR * 2) + c8 * 16;
            cp16(st + so,              &wv[(size_t)lr * 512 + k0 + c8 * 8]);
            cp16(st + TSTR_H * 2 + so, &xf[(size_t)lr * CC + k0 + c8 * 8]);
        }
        CP_COMMIT();
    };

    load_tile(0, 0);
    load_tile(1, 32);

    float acc[4][4][4] = {};
    const int NT = 512 / 32;

    for (int jt = 0; jt < NT; jt++) {
        if (jt == NT - 1) asm volatile("cp.async.wait_group 0;\n" ::: "memory");
        else              asm volatile("cp.async.wait_group 1;\n" ::: "memory");
        __syncthreads();
        if (jt + 2 < NT) load_tile((jt + 2) % 3, (jt + 2) * 32);

        uint32_t st = sbase + (uint32_t)((jt % 3) * V_STG_H * 2);
        #pragma unroll
        for (int kc = 0; kc < 2; kc++) {
            uint32_t af[4][4], bf[4][2];
            lda4(af, st,              wm, lane, kc);
            ldb4(bf, st + TSTR_H * 2, wn, lane, kc);
            #pragma unroll
            for (int mi = 0; mi < 4; mi++)
                #pragma unroll
                for (int ni = 0; ni < 4; ni++)
                    MMA_F16(acc[mi][ni], af[mi], bf[ni]);
        }
    }

    #pragma unroll
    for (int mi = 0; mi < 4; mi++) {
        int cc = c0 + wm * 64 + mi * 16 + g;
        float b0 = bv[cc], b2 = bv[cc + 8];
        #pragma unroll
        for (int ni = 0; ni < 4; ni++) {
            int nn = n0 + wn * 32 + ni * 8 + 2 * c;
            size_t o0 = ((size_t)b * CC + cc) * NN + nn;
            *(uint32_t*)&g_v[o0] = packh2(acc[mi][ni][0] + b0, acc[mi][ni][1] + b0);
            size_t o1 = o0 + (size_t)8 * NN;
            *(uint32_t*)&g_v[o1] = packh2(acc[mi][ni][2] + b2, acc[mi][ni][3] + b2);
        }
    }
}

// ---------------------------------------------------------------------------
// Kernel 2: logits via split-bf16 HMMA (3 passes). S[i][j]=sum_m Q[i][m]K[j][m].
// ---------------------------------------------------------------------------
#define LSTR 72
#define LOGITS_SMEM (4 * 128 * LSTR * 2)

__global__ __launch_bounds__(256)
void logits_kernel() {
    const int j0 = blockIdx.x * 128;
    const int i0 = blockIdx.y * 128;
    const int b  = blockIdx.z;

    extern __shared__ __align__(16) __nv_bfloat16 lsm[];
    __nv_bfloat16* sQh = lsm;
    __nv_bfloat16* sQl = lsm + 128 * LSTR;
    __nv_bfloat16* sKh = lsm + 2 * 128 * LSTR;
    __nv_bfloat16* sKl = lsm + 3 * 128 * LSTR;

    const int tid = threadIdx.x;
    const int wid = tid >> 5, lane = tid & 31;
    const int wm = wid >> 2, wn = wid & 3;
    const int g = lane >> 2, c = lane & 3;

    const size_t qoff = (size_t)b * NN * MIDD;

    #pragma unroll
    for (int i = tid; i < 1024; i += 256) {
        int r = i >> 3, c8 = i & 7;
        size_t go = qoff + (size_t)(i0 + r) * MIDD + c8 * 8;
        size_t ko = qoff + (size_t)(j0 + r) * MIDD + c8 * 8;
        int so = r * LSTR + c8 * 8;
        *(uint4*)&sQh[so] = *(const uint4*)&g_qh[go];
        *(uint4*)&sQl[so] = *(const uint4*)&g_ql[go];
        *(uint4*)&sKh[so] = *(const uint4*)&g_kh[ko];
        *(uint4*)&sKl[so] = *(const uint4*)&g_kl[ko];
    }
    __syncthreads();

    float acc[4][4][4] = {};

    #pragma unroll
    for (int kc = 0; kc < 4; kc++) {
        uint32_t afh[4][4], afl[4][4], bfh[4][2], bfl[4][2];
        #pragma unroll
        for (int mi = 0; mi < 4; mi++) {
            int o = (wm * 64 + mi * 16 + g) * LSTR + kc * 16 + 2 * c;
            afh[mi][0] = *(const uint32_t*)&sQh[o];
            afh[mi][1] = *(const uint32_t*)&sQh[o + 8 * LSTR];
            afh[mi][2] = *(const uint32_t*)&sQh[o + 8];
            afh[mi][3] = *(const uint32_t*)&sQh[o + 8 * LSTR + 8];
            afl[mi][0] = *(const uint32_t*)&sQl[o];
            afl[mi][1] = *(const uint32_t*)&sQl[o + 8 * LSTR];
            afl[mi][2] = *(const uint32_t*)&sQl[o + 8];
            afl[mi][3] = *(const uint32_t*)&sQl[o + 8 * LSTR + 8];
        }
        #pragma unroll
        for (int ni = 0; ni < 4; ni++) {
            int o = (wn * 32 + ni * 8 + g) * LSTR + kc * 16 + 2 * c;
            bfh[ni][0] = *(const uint32_t*)&sKh[o];
            bfh[ni][1] = *(const uint32_t*)&sKh[o + 8];
            bfl[ni][0] = *(const uint32_t*)&sKl[o];
            bfl[ni][1] = *(const uint32_t*)&sKl[o + 8];
        }
        #pragma unroll
        for (int mi = 0; mi < 4; mi++)
            #pragma unroll
            for (int ni = 0; ni < 4; ni++) {
                MMA_BF16(acc[mi][ni], afh[mi], bfh[ni]);
                MMA_BF16(acc[mi][ni], afh[mi], bfl[ni]);
                MMA_BF16(acc[mi][ni], afl[mi], bfh[ni]);
            }
    }

    float* sb = g_s + ((size_t)b * NN + i0) * NN + j0;
    #pragma unroll
    for (int mi = 0; mi < 4; mi++)
        #pragma unroll
        for (int ni = 0; ni < 4; ni++) {
            int r = wm * 64 + mi * 16 + g;
            int cn = wn * 32 + ni * 8 + 2 * c;
            float2 v0 = {acc[mi][ni][0], acc[mi][ni][1]};
            float2 v1 = {acc[mi][ni][2], acc[mi][ni][3]};
            *(float2*)&sb[(size_t)r * NN + cn] = v0;
            *(float2*)&sb[(size_t)(r + 8) * NN + cn] = v1;
        }
}

// ---------------------------------------------------------------------------
// Kernel 3: row softmax. Reads fp32 logits, writes fp16 probs.
// ---------------------------------------------------------------------------
__global__ __launch_bounds__(256, 8)
void softmax_kernel() {
    const int row = blockIdx.x;
    const int b   = blockIdx.y;
    const float* s = g_s + ((size_t)b * NN + row) * NN;
    __half* p = g_p + ((size_t)b * NN + row) * NN;

    const int tid = threadIdx.x;
    float4 v[4];
    #pragma unroll
    for (int i = 0; i < 4; i++)
        v[i] = *(const float4*)&s[tid * 16 + i * 4];

    float m = v[0].x;
    #pragma unroll
    for (int i = 0; i < 4; i++) {
        m = fmaxf(m, v[i].x); m = fmaxf(m, v[i].y);
        m = fmaxf(m, v[i].z); m = fmaxf(m, v[i].w);
    }
    __shared__ float red[8];
    #pragma unroll
    for (int off = 16; off > 0; off >>= 1)
        m = fmaxf(m, __shfl_xor_sync(0xffffffffu, m, off));
    if ((tid & 31) == 0) red[tid >> 5] = m;
    __syncthreads();
    m = red[0];
    #pragma unroll
    for (int w = 1; w < 8; w++) m = fmaxf(m, red[w]);
    __syncthreads();

    float sum = 0.f;
    #pragma unroll
    for (int i = 0; i < 4; i++) {
        v[i].x = __expf(v[i].x - m); sum += v[i].x;
        v[i].y = __expf(v[i].y - m); sum += v[i].y;
        v[i].z = __expf(v[i].z - m); sum += v[i].z;
        v[i].w = __expf(v[i].w - m); sum += v[i].w;
    }
    #pragma unroll
    for (int off = 16; off > 0; off >>= 1)
        sum += __shfl_xor_sync(0xffffffffu, sum, off);
    if ((tid & 31) == 0) red[tid >> 5] = sum;
    __syncthreads();
    sum = 0.f;
    #pragma unroll
    for (int w = 0; w < 8; w++) sum += red[w];
    const float inv = 1.0f / sum;

    uint32_t hh[8];
    #pragma unroll
    for (int i = 0; i < 4; i++) {
        hh[2 * i]     = packh2(v[i].x * inv, v[i].y * inv);
        hh[2 * i + 1] = packh2(v[i].z * inv, v[i].w * inv);
    }
    uint4 u;
    u = make_uint4(hh[0], hh[1], hh[2], hh[3]); *(uint4*)&p[tid * 16] = u;
    u = make_uint4(hh[4], hh[5], hh[6], hh[7]); *(uint4*)&p[tid * 16 + 8] = u;
}

// ---------------------------------------------------------------------------
// Kernel 4: PV via fp16 HMMA, 64x64 warp tiles (CTA 128c x 256n), ldmatrix,
// 3-stage cp.async pipeline.
// Out^T[c][n] = sum_j V[c][j] * P[n][j];  y[b][c][n] = alpha*Out + x.
// ---------------------------------------------------------------------------
#define PV_V_H   (128 * PSTR)                 // V stream halves per stage
#define PV_P_H   (256 * PSTR)                 // P stream halves per stage
#define PV_STG_H (PV_V_H + PV_P_H)            // 15360 halves = 30720 B
#define PV_SMEM  (3 * PV_STG_H * 2)           // 92160 B

__global__ __launch_bounds__(256, 1)
void pv_kernel(const float* __restrict__ x,
               const float* __restrict__ alpha,
               float* __restrict__ y) {
    const int n0 = blockIdx.x * 256;
    const int c0 = blockIdx.y * 128;
    const int b  = blockIdx.z;

    extern __shared__ __align__(16) __half psm[];
    const uint32_t sbase = (uint32_t)__cvta_generic_to_shared(psm);

    const int tid = threadIdx.x;
    const int wid = tid >> 5, lane = tid & 31;
    const int wm = wid >> 2, wn = wid & 3;     // wm: 64-c half, wn: 64-n quarter
    const int g = lane >> 2, c = lane & 3;

    const __half* vv = g_v + (size_t)(b * CC + c0) * NN;
    const __half* pp = g_p + ((size_t)b * NN + n0) * NN;

    auto load_tile = [&](int stage, int j0) {
        uint32_t st = sbase + (uint32_t)(stage * PV_STG_H * 2);
        // V: 128 rows x 4 chunks of 16B
        #pragma unroll
        for (int i = tid; i < 512; i += 256) {
            int r = i >> 2, ch = i & 3;
            cp16(st + r * (PSTR * 2) + ch * 16, &vv[(size_t)r * NN + j0 + ch * 8]);
        }
        // P: 256 rows x 4 chunks of 16B
        #pragma unroll
        for (int i = tid; i < 1024; i += 256) {
            int r = i >> 2, ch = i & 3;
            cp16(st + PV_V_H * 2 + r * (PSTR * 2) + ch * 16,
                 &pp[(size_t)r * NN + j0 + ch * 8]);
        }
        CP_COMMIT();
    };

    load_tile(0, 0);
    load_tile(1, 32);

    float acc[4][8][4] = {};
    const int NT = NN / 32;   // 128

    for (int jt = 0; jt < NT; jt++) {
        if (jt == NT - 1) asm volatile("cp.async.wait_group 0;\n" ::: "memory");
        else              asm volatile("cp.async.wait_group 1;\n" ::: "memory");
        __syncthreads();
        if (jt + 2 < NT) load_tile((jt + 2) % 3, (jt + 2) * 32);

        uint32_t st = sbase + (uint32_t)((jt % 3) * PV_STG_H * 2);
        #pragma unroll
        for (int kc = 0; kc < 2; kc++) {
            uint32_t af[4][4], bf[8][2];
            lda4(af, st, wm, lane, kc);
            ldb4(bf,     st + PV_V_H * 2, wn * 2,     lane, kc);
            ldb4(bf + 4, st + PV_V_H * 2, wn * 2 + 1, lane, kc);
            #pragma unroll
            for (int mi = 0; mi < 4; mi++)
                #pragma unroll
                for (int ni = 0; ni < 8; ni++)
                    MMA_F16(acc[mi][ni], af[mi], bf[ni]);
        }
    }

    const float al = __ldg(alpha);
    #pragma unroll
    for (int mi = 0; mi < 4; mi++)
        #pragma unroll
        for (int ni = 0; ni < 8; ni++) {
            int cc = c0 + wm * 64 + mi * 16 + g;
            int nn = n0 + wn * 64 + ni * 8 + 2 * c;
            size_t o0 = ((size_t)b * CC + cc) * NN + nn;
            float2 xv = *(const float2*)&x[o0];
            float2 o;
            o.x = al * acc[mi][ni][0] + xv.x;
            o.y = al * acc[mi][ni][1] + xv.y;
            *(float2*)&y[o0] = o;
            size_t o1 = o0 + (size_t)8 * NN;
            xv = *(const float2*)&x[o1];
            o.x = al * acc[mi][ni][2] + xv.x;
            o.y = al * acc[mi][ni][3] + xv.y;
            *(float2*)&y[o1] = o;
        }
}

// ---------------------------------------------------------------------------
extern "C" void kernel_launch(void* const* d_in, const int* in_sizes, int n_in,
                              void* d_out, int out_size) {
    const float* x     = (const float*)d_in[0];
    const float* wq    = (const float*)d_in[1];
    const float* bq    = (const float*)d_in[2];
    const float* wk    = (const float*)d_in[3];
    const float* bk    = (const float*)d_in[4];
    const float* wv    = (const float*)d_in[5];
    const float* bv    = (const float*)d_in[6];
    const float* alpha = (const float*)d_in[7];
    float* y = (float*)d_out;

    cudaFuncSetAttribute(proj_qk_kernel,
                         cudaFuncAttributeMaxDynamicSharedMemorySize, QK_SMEM);
    cudaFuncSetAttribute(proj_v_kernel,
                         cudaFuncAttributeMaxDynamicSharedMemorySize, V_SMEM);
    cudaFuncSetAttribute(logits_kernel,
                         cudaFuncAttributeMaxDynamicSharedMemorySize, LOGITS_SMEM);
    cudaFuncSetAttribute(pv_kernel,
                         cudaFuncAttributeMaxDynamicSharedMemorySize, PV_SMEM);

    dim3 blk(256);

    xconv_kernel<<<dim3(NN / 64, CC / 64, BB), blk>>>(x);
    wconv_kernel<<<1280, blk>>>(wq, wk, wv);
    proj_qk_kernel<<<dim3(NN / 128, 1, BB), blk, QK_SMEM>>>(bq, bk);
    proj_v_kernel<<<dim3(NN / 128, CC / 128, BB), blk, V_SMEM>>>(bv);
    logits_kernel<<<dim3(NN / 128, NN / 128, BB), blk, LOGITS_SMEM>>>();
    softmax_kernel<<<dim3(NN, BB), blk>>>();
    pv_kernel<<<dim3(NN / 256, CC / 128, BB), blk, PV_SMEM>>>(x, alpha, y);
}